// round 13
// baseline (speedup 1.0000x reference)
#include <cuda_runtime.h>
#include <cuda_bf16.h>
#include <math.h>
#include <stdint.h>

#define MTOT 131072
#define SPATIAL 128

__device__ __align__(256) __nv_bfloat16 g_qkv[(size_t)MTOT * 384];
__device__ __align__(256) __nv_bfloat16 g_o  [(size_t)MTOT * 128];
__device__ __align__(256) __nv_bfloat16 g_wt [786432];  // 4 layers x 12 images x [128n][128k]

__device__ __forceinline__ float gelu_exact(float a) {
    return 0.5f * a * (1.0f + erff(a * 0.70710678118654752440f));
}

__device__ __forceinline__ uint32_t smem_u32(const void* p) {
    uint32_t a;
    asm("{ .reg .u64 t; cvta.to.shared.u64 t, %1; cvt.u32.u64 %0, t; }" : "=r"(a) : "l"(p));
    return a;
}

#define LDSM4(r0, r1, r2, r3, addr) \
    asm volatile("ldmatrix.sync.aligned.m8n8.x4.shared.b16 {%0,%1,%2,%3}, [%4];" \
                 : "=r"(r0), "=r"(r1), "=r"(r2), "=r"(r3) : "r"(addr))

#define MMA16816(d, a, b) \
    asm volatile("mma.sync.aligned.m16n8k16.row.col.f32.bf16.bf16.f32 " \
                 "{%0,%1,%2,%3},{%4,%5,%6,%7},{%8,%9},{%0,%1,%2,%3};" \
                 : "+f"((d)[0]), "+f"((d)[1]), "+f"((d)[2]), "+f"((d)[3]) \
                 : "r"((a)[0]), "r"((a)[1]), "r"((a)[2]), "r"((a)[3]), \
                   "r"((b)[0]), "r"((b)[1]))

// ---------------------------------------------------------------------------
// Prep: transpose weights to n-major/k-contig bf16 images [128n][128k].
// Per layer (12 imgs): 0-2 qkv n-blocks, 3 proj, 4-7 ff1 n-blocks, 8-11 ff2 k-chunks.
// ---------------------------------------------------------------------------
__global__ __launch_bounds__(256) void k_prep(
    const float* __restrict__ qkv_w, const float* __restrict__ out_w,
    const float* __restrict__ ff_w1, const float* __restrict__ ff_w2)
{
    const int idx = blockIdx.x * 256 + threadIdx.x;   // 0..786431
    const int d   = idx / 196608;
    const int rem = idx % 196608;
    const int img = rem / 16384;
    const int pos = rem % 16384;
    const int n = pos >> 7, k = pos & 127;
    float val;
    if (img < 3)       val = qkv_w[(size_t)(d * 128 + k) * 384 + img * 128 + n];
    else if (img == 3) val = out_w[(size_t)(d * 128 + k) * 128 + n];
    else if (img < 8)  val = ff_w1[(size_t)(d * 128 + k) * 512 + (img - 4) * 128 + n];
    else               val = ff_w2[(size_t)(d * 512 + (img - 8) * 128 + k) * 128 + n];
    g_wt[idx] = __float2bfloat16(val);
}

// ---------------------------------------------------------------------------
// Shared helpers. Warp tile 32x32 (2 mt x 4 nt of m16n8k16), row stride 272 B.
// ---------------------------------------------------------------------------
template<int NT>
__device__ __forceinline__ void stage_B(char* bs, const __nv_bfloat16* img, int tid) {
    const uint4* s4 = (const uint4*)img;
#pragma unroll
    for (int i = 0; i < 2048 / NT; i++) {
        const int u = tid + i * NT;            // 2048 x 16B
        const int row = u >> 4, c8 = u & 15;
        *(uint4*)(bs + (size_t)row * 272 + c8 * 16) = s4[u];
    }
}

__device__ __forceinline__ void gemm_64x128(
    float acc[2][4][4], uint32_t aBase, uint32_t bBase)
{
#pragma unroll
    for (int kk = 0; kk < 8; kk++) {
        uint32_t a[2][4];
#pragma unroll
        for (int mt = 0; mt < 2; mt++)
            LDSM4(a[mt][0], a[mt][1], a[mt][2], a[mt][3],
                  aBase + (uint32_t)(mt * 16 * 272 + kk * 32));
        uint32_t b[4][2];
#pragma unroll
        for (int nt2 = 0; nt2 < 2; nt2++)
            LDSM4(b[nt2*2][0], b[nt2*2][1], b[nt2*2+1][0], b[nt2*2+1][1],
                  bBase + (uint32_t)(nt2 * 16 * 272 + kk * 32));
#pragma unroll
        for (int mt = 0; mt < 2; mt++)
#pragma unroll
            for (int nt = 0; nt < 4; nt++)
                MMA16816(acc[mt][nt], a[mt], b[nt]);
    }
}

// ---------------------------------------------------------------------------
// Kernel 1: y = LN1(x); qkv = y @ Wqkv (3 n-blocks) -> g_qkv bf16. (unchanged)
// ---------------------------------------------------------------------------
__global__ void __launch_bounds__(256, 3) k_qkv(
    const float* __restrict__ X, const float* __restrict__ gamma,
    const float* __restrict__ beta, int d)
{
    extern __shared__ char smem[];
    const uint32_t sbA = smem_u32(smem);
    const uint32_t sbB = sbA + 17408;
    const int tid = threadIdx.x, wid = tid >> 5, lane = tid & 31;
    const int wm = wid >> 2, wn = wid & 3;
    const int m0 = blockIdx.x * 64;
    const __nv_bfloat16* wt = g_wt + (size_t)d * 196608;

    const uint32_t aBase = sbA + (uint32_t)((wm * 32 + (lane & 15)) * 272 + (lane >> 4) * 16);
    const uint32_t bBase = sbB + (uint32_t)((wn * 32 + ((lane >> 4) * 8) + (lane & 7)) * 272
                                            + ((lane >> 3) & 1) * 16);

    {   // stage A: LN1(x) -> bf16
        const int m = tid >> 2, q = tid & 3;
        const float* ap = X + (size_t)(m0 + m) * 128 + q * 32;
        float4 v[8];
#pragma unroll
        for (int j = 0; j < 8; j++) v[j] = ((const float4*)ap)[j];
        float s = 0.f, sq = 0.f;
#pragma unroll
        for (int j = 0; j < 8; j++) {
            s  += v[j].x + v[j].y + v[j].z + v[j].w;
            sq += v[j].x*v[j].x + v[j].y*v[j].y + v[j].z*v[j].z + v[j].w*v[j].w;
        }
        s  += __shfl_xor_sync(0xffffffffu, s , 1);
        sq += __shfl_xor_sync(0xffffffffu, sq, 1);
        s  += __shfl_xor_sync(0xffffffffu, s , 2);
        sq += __shfl_xor_sync(0xffffffffu, sq, 2);
        const float mean = s * (1.f / 128.f);
        const float rstd = rsqrtf(sq * (1.f / 128.f) - mean * mean + 1e-3f);
        char* arow = smem + (size_t)m * 272 + q * 64;
#pragma unroll
        for (int j = 0; j < 4; j++) {
            const int k = q * 32 + j * 8;
            const float4 f0 = v[2*j], f1 = v[2*j+1];
            const float4 g0 = *(const float4*)(gamma + k);
            const float4 g1 = *(const float4*)(gamma + k + 4);
            const float4 b0 = *(const float4*)(beta + k);
            const float4 b1 = *(const float4*)(beta + k + 4);
            __nv_bfloat16 t8[8];
            t8[0]=__float2bfloat16((f0.x-mean)*rstd*g0.x+b0.x);
            t8[1]=__float2bfloat16((f0.y-mean)*rstd*g0.y+b0.y);
            t8[2]=__float2bfloat16((f0.z-mean)*rstd*g0.z+b0.z);
            t8[3]=__float2bfloat16((f0.w-mean)*rstd*g0.w+b0.w);
            t8[4]=__float2bfloat16((f1.x-mean)*rstd*g1.x+b1.x);
            t8[5]=__float2bfloat16((f1.y-mean)*rstd*g1.y+b1.y);
            t8[6]=__float2bfloat16((f1.z-mean)*rstd*g1.z+b1.z);
            t8[7]=__float2bfloat16((f1.w-mean)*rstd*g1.w+b1.w);
            *(uint4*)(arow + j * 16) = *(const uint4*)t8;
        }
    }

    for (int nb = 0; nb < 3; nb++) {
        if (nb) __syncthreads();
        stage_B<256>(smem + 17408, wt + (size_t)nb * 16384, tid);
        __syncthreads();
        float acc[2][4][4] = {};
        gemm_64x128(acc, aBase, bBase);
#pragma unroll
        for (int mt = 0; mt < 2; mt++)
#pragma unroll
            for (int nt = 0; nt < 4; nt++) {
                const int r = m0 + wm * 32 + mt * 16 + (lane >> 2);
                const int c = nb * 128 + wn * 32 + nt * 8 + (lane & 3) * 2;
#pragma unroll
                for (int hrow = 0; hrow < 2; hrow++)
                    *(__nv_bfloat162*)(g_qkv + (size_t)(r + hrow * 8) * 384 + c) =
                        __floats2bfloat162_rn(acc[mt][nt][hrow*2], acc[mt][nt][hrow*2+1]);
            }
    }
}

// ---------------------------------------------------------------------------
// FUSED proj+LN2+ff1+gelu+ff2: CTA = 128 tokens, 512 threads (16 warps 4Mx4N),
// ping-pong B buffers so every weight stage overlaps a gemm.
// smem: A 34816 @0, B0 @34816, B1 @69632, H @104448, Xs fp32 128x132 @139264.
// Total 206848 B -> 1 CTA/SM.
// ---------------------------------------------------------------------------
__global__ void __launch_bounds__(512) k_fused(
    const float* __restrict__ bp, const float* __restrict__ ln2_g,
    const float* __restrict__ ln2_b, const float* __restrict__ b1,
    const float* __restrict__ b2, float* __restrict__ X, int d)
{
    extern __shared__ char smem[];
    const uint32_t sbA = smem_u32(smem);
    const uint32_t sbB0 = sbA + 34816;
    const uint32_t sbB1 = sbA + 69632;
    const uint32_t sbH  = sbA + 104448;
    float* Xs = (float*)(smem + 139264);             // [128][132] fp32
    const int tid = threadIdx.x, wid = tid >> 5, lane = tid & 31;
    const int wm = wid >> 2, wn = wid & 3;           // 4 M-warps x 4 N-warps
    const int m0 = blockIdx.x * 128;
    const __nv_bfloat16* wt = g_wt + (size_t)d * 196608;

    const uint32_t lA = (uint32_t)((wm * 32 + (lane & 15)) * 272 + (lane >> 4) * 16);
    const uint32_t aBase = sbA + lA;
    const uint32_t hBase = sbH + lA;
    const uint32_t lB = (uint32_t)((wn * 32 + ((lane >> 4) * 8) + (lane & 7)) * 272
                                   + ((lane >> 3) & 1) * 16);

    // ---- prologue: stage A = o (bf16 copy), B0 = proj image ----
    {
        const int m = tid >> 2, q = tid & 3;
        const __nv_bfloat16* ap = g_o + (size_t)(m0 + m) * 128 + q * 32;
        char* arow = smem + (size_t)m * 272 + q * 64;
#pragma unroll
        for (int j = 0; j < 4; j++)
            *(uint4*)(arow + j * 16) = ((const uint4*)ap)[j];
        stage_B<512>(smem + 34816, wt + 3 * 16384, tid);
    }
    __syncthreads();

    // ---- proj gemm (B0) overlapped with staging B1 = ff1_0 ----
    stage_B<512>(smem + 69632, wt + 4 * 16384, tid);
    {
        float acc[2][4][4] = {};
        gemm_64x128(acc, aBase, sbB0 + lB);
#pragma unroll
        for (int mt = 0; mt < 2; mt++)
#pragma unroll
            for (int nt = 0; nt < 4; nt++) {
                const int rl = wm * 32 + mt * 16 + (lane >> 2);
                const int c  = wn * 32 + nt * 8 + (lane & 3) * 2;
                const float2 bv = *(const float2*)(bp + c);
#pragma unroll
                for (int hrow = 0; hrow < 2; hrow++) {
                    const int rr = rl + hrow * 8;
                    const float2 xo = *(const float2*)(X + (size_t)(m0 + rr) * 128 + c);
                    *(float2*)&Xs[rr * 132 + c] = make_float2(
                        xo.x + acc[mt][nt][hrow*2]   + bv.x,
                        xo.y + acc[mt][nt][hrow*2+1] + bv.y);
                }
            }
    }
    __syncthreads();

    // ---- LN2 (Xs -> A) overlapped with staging B0 = ff2_0 ----
    stage_B<512>(smem + 34816, wt + 8 * 16384, tid);
    {
        const int m = tid >> 2, q = tid & 3;
        const float* xp = &Xs[m * 132 + q * 32];
        float4 v[8];
#pragma unroll
        for (int j = 0; j < 8; j++) v[j] = ((const float4*)xp)[j];
        float s = 0.f, sq = 0.f;
#pragma unroll
        for (int j = 0; j < 8; j++) {
            s  += v[j].x + v[j].y + v[j].z + v[j].w;
            sq += v[j].x*v[j].x + v[j].y*v[j].y + v[j].z*v[j].z + v[j].w*v[j].w;
        }
        s  += __shfl_xor_sync(0xffffffffu, s , 1);
        sq += __shfl_xor_sync(0xffffffffu, sq, 1);
        s  += __shfl_xor_sync(0xffffffffu, s , 2);
        sq += __shfl_xor_sync(0xffffffffu, sq, 2);
        const float mean = s * (1.f / 128.f);
        const float rstd = rsqrtf(sq * (1.f / 128.f) - mean * mean + 1e-3f);
        char* arow = smem + (size_t)m * 272 + q * 64;
#pragma unroll
        for (int j = 0; j < 4; j++) {
            const int k = q * 32 + j * 8;
            const float4 f0 = v[2*j], f1 = v[2*j+1];
            const float4 g0 = *(const float4*)(ln2_g + k);
            const float4 g1 = *(const float4*)(ln2_g + k + 4);
            const float4 c0 = *(const float4*)(ln2_b + k);
            const float4 c1 = *(const float4*)(ln2_b + k + 4);
            __nv_bfloat16 t8[8];
            t8[0]=__float2bfloat16((f0.x-mean)*rstd*g0.x+c0.x);
            t8[1]=__float2bfloat16((f0.y-mean)*rstd*g0.y+c0.y);
            t8[2]=__float2bfloat16((f0.z-mean)*rstd*g0.z+c0.z);
            t8[3]=__float2bfloat16((f0.w-mean)*rstd*g0.w+c0.w);
            t8[4]=__float2bfloat16((f1.x-mean)*rstd*g1.x+c1.x);
            t8[5]=__float2bfloat16((f1.y-mean)*rstd*g1.y+c1.y);
            t8[6]=__float2bfloat16((f1.z-mean)*rstd*g1.z+c1.z);
            t8[7]=__float2bfloat16((f1.w-mean)*rstd*g1.w+c1.w);
            *(uint4*)(arow + j * 16) = *(const uint4*)t8;
        }
    }
    __syncthreads();

    // ---- ff1/ff2 pipeline: B1 cycles ff1 images, B0 cycles ff2 images ----
    float acc2[2][4][4] = {};
    for (int i = 0; i < 4; i++) {
        // gemm ff1_i (A, B1); stage B0=ff2_i was done in previous slot (or prologue)
        {
            float acc[2][4][4] = {};
            gemm_64x128(acc, aBase, sbB1 + lB);
#pragma unroll
            for (int mt = 0; mt < 2; mt++)
#pragma unroll
                for (int nt = 0; nt < 4; nt++) {
                    const int rl = wm * 32 + mt * 16 + (lane >> 2);
                    const int c  = wn * 32 + nt * 8 + (lane & 3) * 2;
                    const float2 bv = *(const float2*)(b1 + i * 128 + c);
#pragma unroll
                    for (int hrow = 0; hrow < 2; hrow++) {
                        const int rr = rl + hrow * 8;
                        *(__nv_bfloat162*)(smem + 104448 + (size_t)rr * 272 + c * 2) =
                            __floats2bfloat162_rn(gelu_exact(acc[mt][nt][hrow*2]   + bv.x),
                                                  gelu_exact(acc[mt][nt][hrow*2+1] + bv.y));
                    }
                }
        }
        __syncthreads();                         // H ready; B1 free
        if (i < 3)                               // stage B1 = ff1_{i+1} during ff2 gemm
            stage_B<512>(smem + 69632, wt + (size_t)(5 + i) * 16384, tid);
        gemm_64x128(acc2, hBase, sbB0 + lB);     // acc2 += h_i @ W2_i
        __syncthreads();                         // B0/H free; B1 staged
        if (i < 3)                               // stage B0 = ff2_{i+1} during ff1 gemm (next iter)
            stage_B<512>(smem + 34816, wt + (size_t)(9 + i) * 16384, tid);
    }

    // ---- final epilogue: X = Xs + acc2 + b2 ----
#pragma unroll
    for (int mt = 0; mt < 2; mt++)
#pragma unroll
        for (int nt = 0; nt < 4; nt++) {
            const int rl = wm * 32 + mt * 16 + (lane >> 2);
            const int c  = wn * 32 + nt * 8 + (lane & 3) * 2;
            const float2 bv = *(const float2*)(b2 + c);
#pragma unroll
            for (int hrow = 0; hrow < 2; hrow++) {
                const int rr = rl + hrow * 8;
                const float2 xs = *(const float2*)&Xs[rr * 132 + c];
                *(float2*)(X + (size_t)(m0 + rr) * 128 + c) = make_float2(
                    xs.x + acc2[mt][nt][hrow*2]   + bv.x,
                    xs.y + acc2[mt][nt][hrow*2+1] + bv.y);
            }
        }
}

// ---------------------------------------------------------------------------
// Local 3x3 attention: bf16 global traffic, fp32 smem compute. (unchanged)
// ---------------------------------------------------------------------------
__global__ __launch_bounds__(256) void k_attn()
{
    extern __shared__ float sm[];
    float* ksh = sm;              // 18*18*36
    float* vsh = sm + 11664;
    float* qo  = sm + 2 * 11664;  // 256*36
    const int tid = threadIdx.x;
    const int b   = blockIdx.z;
    const int ti0 = blockIdx.y * 16, tj0 = blockIdx.x * 16;
    const size_t img_base = (size_t)b * (SPATIAL * SPATIAL);

    for (int head = 0; head < 4; head++) {
        if (head) __syncthreads();
        const int qoff = head * 32, koff = 128 + head * 32, voff = 256 + head * 32;
        for (int idx = tid; idx < 18 * 18 * 16; idx += 256) {
            const int c2 = (idx & 15) * 2;
            const int rc = idx >> 4;
            const int r = rc / 18, cl = rc % 18;
            const int gi = ti0 + r - 1, gj = tj0 + cl - 1;
            float k0 = 0.f, k1 = 0.f, v0 = 0.f, v1 = 0.f;
            if (gi >= 0 && gi < SPATIAL && gj >= 0 && gj < SPATIAL) {
                const __nv_bfloat16* p = g_qkv + (img_base + (size_t)gi * SPATIAL + gj) * 384;
                const __nv_bfloat162 kp = *(const __nv_bfloat162*)(p + koff + c2);
                const __nv_bfloat162 vp = *(const __nv_bfloat162*)(p + voff + c2);
                k0 = __bfloat162float(kp.x); k1 = __bfloat162float(kp.y);
                v0 = __bfloat162float(vp.x); v1 = __bfloat162float(vp.y);
            }
            ksh[rc * 36 + c2] = k0; ksh[rc * 36 + c2 + 1] = k1;
            vsh[rc * 36 + c2] = v0; vsh[rc * 36 + c2 + 1] = v1;
        }
        for (int idx = tid; idx < 256 * 16; idx += 256) {
            const int c2 = (idx & 15) * 2, t = idx >> 4;
            const int gi = ti0 + (t >> 4), gj = tj0 + (t & 15);
            const __nv_bfloat162 qp = *(const __nv_bfloat162*)(
                g_qkv + (img_base + (size_t)gi * SPATIAL + gj) * 384 + qoff + c2);
            qo[t * 36 + c2] = __bfloat162float(qp.x);
            qo[t * 36 + c2 + 1] = __bfloat162float(qp.y);
        }
        __syncthreads();

        const int t = tid, lti = t >> 4, ltj = t & 15;
        float q[32];
#pragma unroll
        for (int i = 0; i < 8; i++) {
            float4 f = *(const float4*)&qo[t * 36 + i * 4];
            q[4*i+0]=f.x; q[4*i+1]=f.y; q[4*i+2]=f.z; q[4*i+3]=f.w;
        }
        float lg[9];
#pragma unroll
        for (int nb = 0; nb < 9; nb++) {
            const float* kp = &ksh[((lti + nb/3)*18 + (ltj + nb%3))*36];
            float dd = 0.f;
#pragma unroll
            for (int i = 0; i < 8; i++) {
                float4 f = *(const float4*)&kp[i*4];
                dd += q[4*i]*f.x + q[4*i+1]*f.y + q[4*i+2]*f.z + q[4*i+3]*f.w;
            }
            lg[nb] = dd * 0.17677669529663687f;
        }
        float mx = lg[0];
#pragma unroll
        for (int nb = 1; nb < 9; nb++) mx = fmaxf(mx, lg[nb]);
        float p9[9], Z = 0.f;
#pragma unroll
        for (int nb = 0; nb < 9; nb++) { p9[nb] = expf(lg[nb] - mx); Z += p9[nb]; }
        const float inv = 1.f / Z;
        float o[32] = {};
#pragma unroll
        for (int nb = 0; nb < 9; nb++) {
            const float wgt = p9[nb] * inv;
            const float* vp = &vsh[((lti + nb/3)*18 + (ltj + nb%3))*36];
#pragma unroll
            for (int i = 0; i < 8; i++) {
                float4 f = *(const float4*)&vp[i*4];
                o[4*i+0]+=wgt*f.x; o[4*i+1]+=wgt*f.y; o[4*i+2]+=wgt*f.z; o[4*i+3]+=wgt*f.w;
            }
        }
#pragma unroll
        for (int i = 0; i < 8; i++)
            *(float4*)&qo[t*36 + i*4] = make_float4(o[4*i], o[4*i+1], o[4*i+2], o[4*i+3]);
        __syncthreads();
        for (int idx = tid; idx < 256 * 16; idx += 256) {
            const int c2 = (idx & 15) * 2, tt = idx >> 4;
            const int gi = ti0 + (tt >> 4), gj = tj0 + (tt & 15);
            *(__nv_bfloat162*)(g_o + (img_base + (size_t)gi * SPATIAL + gj) * 128
                               + head * 32 + c2) =
                __floats2bfloat162_rn(qo[tt * 36 + c2], qo[tt * 36 + c2 + 1]);
        }
    }
}

// ---------------------------------------------------------------------------
extern "C" void kernel_launch(void* const* d_in, const int* in_sizes, int n_in,
                              void* d_out, int out_size)
{
    (void)in_sizes; (void)n_in; (void)out_size;
    const float* x_in  = (const float*)d_in[0];
    const float* ln1_g = (const float*)d_in[1];
    const float* ln1_b = (const float*)d_in[2];
    const float* qkv_w = (const float*)d_in[3];
    const float* out_w = (const float*)d_in[4];
    const float* out_b = (const float*)d_in[5];
    const float* ln2_g = (const float*)d_in[6];
    const float* ln2_b = (const float*)d_in[7];
    const float* ff_w1 = (const float*)d_in[8];
    const float* ff_b1 = (const float*)d_in[9];
    const float* ff_w2 = (const float*)d_in[10];
    const float* ff_b2 = (const float*)d_in[11];
    float* X = (float*)d_out;

    const int SM_QKV   = 52224;
    const int SM_FUSED = 206848;
    const int SM_ATTN  = (2 * 11664 + 9216) * 4;
    cudaFuncSetAttribute(k_qkv,   cudaFuncAttributeMaxDynamicSharedMemorySize, SM_QKV);
    cudaFuncSetAttribute(k_fused, cudaFuncAttributeMaxDynamicSharedMemorySize, SM_FUSED);
    cudaFuncSetAttribute(k_attn,  cudaFuncAttributeMaxDynamicSharedMemorySize, SM_ATTN);

    cudaMemcpyAsync(X, x_in, (size_t)MTOT * 128 * sizeof(float),
                    cudaMemcpyDeviceToDevice, 0);
    k_prep<<<3072, 256>>>(qkv_w, out_w, ff_w1, ff_w2);

    dim3 gAttn(8, 8, 8);
    for (int d = 0; d < 4; d++) {
        k_qkv<<<MTOT / 64, 256, SM_QKV>>>(X, ln1_g + d*128, ln1_b + d*128, d);
        k_attn<<<gAttn, 256, SM_ATTN>>>();
        k_fused<<<MTOT / 128, 512, SM_FUSED>>>(out_b + d*128, ln2_g + d*128, ln2_b + d*128,
                                               ff_b1 + d*512, ff_b2 + d*128, X, d);
    }
}

// round 14
// speedup vs baseline: 1.0623x; 1.0623x over previous
#include <cuda_runtime.h>
#include <cuda_bf16.h>
#include <math.h>
#include <stdint.h>

#define MTOT 131072
#define SPATIAL 128

__device__ __align__(256) __nv_bfloat16 g_qkv[(size_t)MTOT * 384];
__device__ __align__(256) __nv_bfloat16 g_o  [(size_t)MTOT * 128];
__device__ __align__(256) __nv_bfloat16 g_wt [786432];  // 4 layers x 12 images x [128n][128k]

__device__ __forceinline__ float gelu_exact(float a) {
    return 0.5f * a * (1.0f + erff(a * 0.70710678118654752440f));
}

__device__ __forceinline__ uint32_t smem_u32(const void* p) {
    uint32_t a;
    asm("{ .reg .u64 t; cvta.to.shared.u64 t, %1; cvt.u32.u64 %0, t; }" : "=r"(a) : "l"(p));
    return a;
}

#define LDSM4(r0, r1, r2, r3, addr) \
    asm volatile("ldmatrix.sync.aligned.m8n8.x4.shared.b16 {%0,%1,%2,%3}, [%4];" \
                 : "=r"(r0), "=r"(r1), "=r"(r2), "=r"(r3) : "r"(addr))

#define MMA16816(d, a, b) \
    asm volatile("mma.sync.aligned.m16n8k16.row.col.f32.bf16.bf16.f32 " \
                 "{%0,%1,%2,%3},{%4,%5,%6,%7},{%8,%9},{%0,%1,%2,%3};" \
                 : "+f"((d)[0]), "+f"((d)[1]), "+f"((d)[2]), "+f"((d)[3]) \
                 : "r"((a)[0]), "r"((a)[1]), "r"((a)[2]), "r"((a)[3]), \
                   "r"((b)[0]), "r"((b)[1]))

// ---------------------------------------------------------------------------
// Prep: transpose weights to n-major/k-contig bf16 images [128n][128k].
// Per layer (12 imgs): 0-2 qkv n-blocks, 3 proj, 4-7 ff1 n-blocks, 8-11 ff2 k-chunks.
// ---------------------------------------------------------------------------
__global__ __launch_bounds__(256) void k_prep(
    const float* __restrict__ qkv_w, const float* __restrict__ out_w,
    const float* __restrict__ ff_w1, const float* __restrict__ ff_w2)
{
    const int idx = blockIdx.x * 256 + threadIdx.x;   // 0..786431
    const int d   = idx / 196608;
    const int rem = idx % 196608;
    const int img = rem / 16384;
    const int pos = rem % 16384;
    const int n = pos >> 7, k = pos & 127;
    float val;
    if (img < 3)       val = qkv_w[(size_t)(d * 128 + k) * 384 + img * 128 + n];
    else if (img == 3) val = out_w[(size_t)(d * 128 + k) * 128 + n];
    else if (img < 8)  val = ff_w1[(size_t)(d * 128 + k) * 512 + (img - 4) * 128 + n];
    else               val = ff_w2[(size_t)(d * 512 + (img - 8) * 128 + k) * 128 + n];
    g_wt[idx] = __float2bfloat16(val);
}

// ---------------------------------------------------------------------------
// Shared helpers. Warp tile 32x32 (2 mt x 4 nt of m16n8k16), row stride 272 B.
// ---------------------------------------------------------------------------
__device__ __forceinline__ void stage_B(char* bs, const __nv_bfloat16* img, int tid) {
    const uint4* s4 = (const uint4*)img;
#pragma unroll
    for (int i = 0; i < 8; i++) {
        const int u = tid + i * 256;            // 2048 x 16B
        const int row = u >> 4, c8 = u & 15;
        *(uint4*)(bs + (size_t)row * 272 + c8 * 16) = s4[u];
    }
}

__device__ __forceinline__ void gemm_64x128(
    float acc[2][4][4], uint32_t aBase, uint32_t bBase)
{
#pragma unroll
    for (int kk = 0; kk < 8; kk++) {
        uint32_t a[2][4];
#pragma unroll
        for (int mt = 0; mt < 2; mt++)
            LDSM4(a[mt][0], a[mt][1], a[mt][2], a[mt][3],
                  aBase + (uint32_t)(mt * 16 * 272 + kk * 32));
        uint32_t b[4][2];
#pragma unroll
        for (int nt2 = 0; nt2 < 2; nt2++)
            LDSM4(b[nt2*2][0], b[nt2*2][1], b[nt2*2+1][0], b[nt2*2+1][1],
                  bBase + (uint32_t)(nt2 * 16 * 272 + kk * 32));
#pragma unroll
        for (int mt = 0; mt < 2; mt++)
#pragma unroll
            for (int nt = 0; nt < 4; nt++)
                MMA16816(acc[mt][nt], a[mt], b[nt]);
    }
}

// LayerNorm of 64 rows from a fp32 smem tile (stride 132) -> bf16 A tile (stride 272).
__device__ __forceinline__ void ln_rows64(
    char* smem, const float* Xs, const float* g, const float* b, int tid)
{
    const int m = tid >> 2, q = tid & 3;
    const float* xp = &Xs[m * 132 + q * 32];
    float4 v[8];
#pragma unroll
    for (int j = 0; j < 8; j++) v[j] = ((const float4*)xp)[j];
    float s = 0.f, sq = 0.f;
#pragma unroll
    for (int j = 0; j < 8; j++) {
        s  += v[j].x + v[j].y + v[j].z + v[j].w;
        sq += v[j].x*v[j].x + v[j].y*v[j].y + v[j].z*v[j].z + v[j].w*v[j].w;
    }
    s  += __shfl_xor_sync(0xffffffffu, s , 1);
    sq += __shfl_xor_sync(0xffffffffu, sq, 1);
    s  += __shfl_xor_sync(0xffffffffu, s , 2);
    sq += __shfl_xor_sync(0xffffffffu, sq, 2);
    const float mean = s * (1.f / 128.f);
    const float rstd = rsqrtf(sq * (1.f / 128.f) - mean * mean + 1e-3f);
    char* arow = smem + (size_t)m * 272 + q * 64;
#pragma unroll
    for (int j = 0; j < 4; j++) {
        const int k = q * 32 + j * 8;
        const float4 f0 = v[2*j], f1 = v[2*j+1];
        const float4 g0 = *(const float4*)(g + k);
        const float4 g1 = *(const float4*)(g + k + 4);
        const float4 c0 = *(const float4*)(b + k);
        const float4 c1 = *(const float4*)(b + k + 4);
        __nv_bfloat16 t8[8];
        t8[0]=__float2bfloat16((f0.x-mean)*rstd*g0.x+c0.x);
        t8[1]=__float2bfloat16((f0.y-mean)*rstd*g0.y+c0.y);
        t8[2]=__float2bfloat16((f0.z-mean)*rstd*g0.z+c0.z);
        t8[3]=__float2bfloat16((f0.w-mean)*rstd*g0.w+c0.w);
        t8[4]=__float2bfloat16((f1.x-mean)*rstd*g1.x+c1.x);
        t8[5]=__float2bfloat16((f1.y-mean)*rstd*g1.y+c1.y);
        t8[6]=__float2bfloat16((f1.z-mean)*rstd*g1.z+c1.z);
        t8[7]=__float2bfloat16((f1.w-mean)*rstd*g1.w+c1.w);
        *(uint4*)(arow + j * 16) = *(const uint4*)t8;
    }
}

// ---------------------------------------------------------------------------
// Kernel 1 (layer 0 only): y = LN1(x); qkv = y @ Wqkv -> g_qkv bf16.
// ---------------------------------------------------------------------------
__global__ void __launch_bounds__(256, 3) k_qkv(
    const float* __restrict__ X, const float* __restrict__ gamma,
    const float* __restrict__ beta, int d)
{
    extern __shared__ char smem[];
    const uint32_t sbA = smem_u32(smem);
    const uint32_t sbB = sbA + 17408;
    const int tid = threadIdx.x, wid = tid >> 5, lane = tid & 31;
    const int wm = wid >> 2, wn = wid & 3;
    const int m0 = blockIdx.x * 64;
    const __nv_bfloat16* wt = g_wt + (size_t)d * 196608;

    const uint32_t aBase = sbA + (uint32_t)((wm * 32 + (lane & 15)) * 272 + (lane >> 4) * 16);
    const uint32_t bBase = sbB + (uint32_t)((wn * 32 + ((lane >> 4) * 8) + (lane & 7)) * 272
                                            + ((lane >> 3) & 1) * 16);

    {   // stage A: LN1(x) from GLOBAL fp32 x
        const int m = tid >> 2, q = tid & 3;
        const float* ap = X + (size_t)(m0 + m) * 128 + q * 32;
        float4 v[8];
#pragma unroll
        for (int j = 0; j < 8; j++) v[j] = ((const float4*)ap)[j];
        float s = 0.f, sq = 0.f;
#pragma unroll
        for (int j = 0; j < 8; j++) {
            s  += v[j].x + v[j].y + v[j].z + v[j].w;
            sq += v[j].x*v[j].x + v[j].y*v[j].y + v[j].z*v[j].z + v[j].w*v[j].w;
        }
        s  += __shfl_xor_sync(0xffffffffu, s , 1);
        sq += __shfl_xor_sync(0xffffffffu, sq, 1);
        s  += __shfl_xor_sync(0xffffffffu, s , 2);
        sq += __shfl_xor_sync(0xffffffffu, sq, 2);
        const float mean = s * (1.f / 128.f);
        const float rstd = rsqrtf(sq * (1.f / 128.f) - mean * mean + 1e-3f);
        char* arow = smem + (size_t)m * 272 + q * 64;
#pragma unroll
        for (int j = 0; j < 4; j++) {
            const int k = q * 32 + j * 8;
            const float4 f0 = v[2*j], f1 = v[2*j+1];
            const float4 g0 = *(const float4*)(gamma + k);
            const float4 g1 = *(const float4*)(gamma + k + 4);
            const float4 b0 = *(const float4*)(beta + k);
            const float4 b1 = *(const float4*)(beta + k + 4);
            __nv_bfloat16 t8[8];
            t8[0]=__float2bfloat16((f0.x-mean)*rstd*g0.x+b0.x);
            t8[1]=__float2bfloat16((f0.y-mean)*rstd*g0.y+b0.y);
            t8[2]=__float2bfloat16((f0.z-mean)*rstd*g0.z+b0.z);
            t8[3]=__float2bfloat16((f0.w-mean)*rstd*g0.w+b0.w);
            t8[4]=__float2bfloat16((f1.x-mean)*rstd*g1.x+b1.x);
            t8[5]=__float2bfloat16((f1.y-mean)*rstd*g1.y+b1.y);
            t8[6]=__float2bfloat16((f1.z-mean)*rstd*g1.z+b1.z);
            t8[7]=__float2bfloat16((f1.w-mean)*rstd*g1.w+b1.w);
            *(uint4*)(arow + j * 16) = *(const uint4*)t8;
        }
    }

    for (int nb = 0; nb < 3; nb++) {
        if (nb) __syncthreads();
        stage_B(smem + 17408, wt + (size_t)nb * 16384, tid);
        __syncthreads();
        float acc[2][4][4] = {};
        gemm_64x128(acc, aBase, bBase);
#pragma unroll
        for (int mt = 0; mt < 2; mt++)
#pragma unroll
            for (int nt = 0; nt < 4; nt++) {
                const int r = m0 + wm * 32 + mt * 16 + (lane >> 2);
                const int c = nb * 128 + wn * 32 + nt * 8 + (lane & 3) * 2;
#pragma unroll
                for (int hrow = 0; hrow < 2; hrow++)
                    *(__nv_bfloat162*)(g_qkv + (size_t)(r + hrow * 8) * 384 + c) =
                        __floats2bfloat162_rn(acc[mt][nt][hrow*2], acc[mt][nt][hrow*2+1]);
            }
    }
}

// ---------------------------------------------------------------------------
// FUSED: x += o@Wp + bp; y = LN2(x); h_i = gelu(y@W1_i+b1_i); x += sum h_i@W2_i + b2;
// then (do_qkv) LN1_next(x) and qkv GEMMs for layer d+1 straight from smem Xs.
// CTA = 64 tokens, 256 threads (8 warps 2Mx4N). R11-proven structure.
// smem: A 17408 @0, B 34816 @17408, H 17408 @52224, Xs fp32 64x132 @69632.
// Total 103424 B -> 2 CTAs/SM.
// ---------------------------------------------------------------------------
__global__ void __launch_bounds__(256, 2) k_fused(
    const float* __restrict__ bp, const float* __restrict__ ln2_g,
    const float* __restrict__ ln2_b, const float* __restrict__ b1,
    const float* __restrict__ b2, float* __restrict__ X, int d,
    const float* __restrict__ ln1g_n, const float* __restrict__ ln1b_n, int do_qkv)
{
    extern __shared__ char smem[];
    const uint32_t sbA = smem_u32(smem);
    const uint32_t sbB = sbA + 17408;
    const uint32_t sbH = sbA + 52224;
    float* Xs = (float*)(smem + 69632);              // [64][132] fp32
    const int tid = threadIdx.x, wid = tid >> 5, lane = tid & 31;
    const int wm = wid >> 2, wn = wid & 3;
    const int m0 = blockIdx.x * 64;
    const __nv_bfloat16* wt = g_wt + (size_t)d * 196608;

    const uint32_t lA = (uint32_t)((wm * 32 + (lane & 15)) * 272 + (lane >> 4) * 16);
    const uint32_t aBase = sbA + lA;
    const uint32_t hBase = sbH + lA;
    const uint32_t bBase = sbB + (uint32_t)((wn * 32 + ((lane >> 4) * 8) + (lane & 7)) * 272
                                            + ((lane >> 3) & 1) * 16);

    // ---- phase 1: proj ----
    {
        const int m = tid >> 2, q = tid & 3;
        const __nv_bfloat16* ap = g_o + (size_t)(m0 + m) * 128 + q * 32;
        char* arow = smem + (size_t)m * 272 + q * 64;
#pragma unroll
        for (int j = 0; j < 4; j++)
            *(uint4*)(arow + j * 16) = ((const uint4*)ap)[j];
        stage_B(smem + 17408, wt + 3 * 16384, tid);
    }
    __syncthreads();
    {
        float acc[2][4][4] = {};
        gemm_64x128(acc, aBase, bBase);
#pragma unroll
        for (int mt = 0; mt < 2; mt++)
#pragma unroll
            for (int nt = 0; nt < 4; nt++) {
                const int rl = wm * 32 + mt * 16 + (lane >> 2);
                const int c  = wn * 32 + nt * 8 + (lane & 3) * 2;
                const float2 bv = *(const float2*)(bp + c);
#pragma unroll
                for (int hrow = 0; hrow < 2; hrow++) {
                    const int rr = rl + hrow * 8;
                    const float2 xo = *(const float2*)(X + (size_t)(m0 + rr) * 128 + c);
                    *(float2*)&Xs[rr * 132 + c] = make_float2(
                        xo.x + acc[mt][nt][hrow*2]   + bv.x,
                        xo.y + acc[mt][nt][hrow*2+1] + bv.y);
                }
            }
    }
    __syncthreads();

    // ---- phase 2: LN2 from Xs -> A ----
    ln_rows64(smem, Xs, ln2_g, ln2_b, tid);

    // ---- phase 3: interleaved ff1/ff2 over 4 128-col chunks ----
    float acc2[2][4][4] = {};
    for (int i = 0; i < 4; i++) {
        __syncthreads();                          // B/H safe to overwrite
        stage_B(smem + 17408, wt + (size_t)(4 + i) * 16384, tid);
        __syncthreads();
        {   // h_i = gelu(y @ W1_i + b1_i) -> H smem (bf16)
            float acc[2][4][4] = {};
            gemm_64x128(acc, aBase, bBase);
#pragma unroll
            for (int mt = 0; mt < 2; mt++)
#pragma unroll
                for (int nt = 0; nt < 4; nt++) {
                    const int rl = wm * 32 + mt * 16 + (lane >> 2);
                    const int c  = wn * 32 + nt * 8 + (lane & 3) * 2;
                    const float2 bv = *(const float2*)(b1 + i * 128 + c);
#pragma unroll
                    for (int hrow = 0; hrow < 2; hrow++) {
                        const int rr = rl + hrow * 8;
                        *(__nv_bfloat162*)(smem + 52224 + (size_t)rr * 272 + c * 2) =
                            __floats2bfloat162_rn(gelu_exact(acc[mt][nt][hrow*2]   + bv.x),
                                                  gelu_exact(acc[mt][nt][hrow*2+1] + bv.y));
                    }
                }
        }
        __syncthreads();                          // H ready; B readers done
        stage_B(smem + 17408, wt + (size_t)(8 + i) * 16384, tid);
        __syncthreads();
        gemm_64x128(acc2, hBase, bBase);          // acc2 += h_i @ W2_i
    }

    // ---- final epilogue: X = Xs + acc2 + b2 (global + back into Xs) ----
#pragma unroll
    for (int mt = 0; mt < 2; mt++)
#pragma unroll
        for (int nt = 0; nt < 4; nt++) {
            const int rl = wm * 32 + mt * 16 + (lane >> 2);
            const int c  = wn * 32 + nt * 8 + (lane & 3) * 2;
            const float2 bv = *(const float2*)(b2 + c);
#pragma unroll
            for (int hrow = 0; hrow < 2; hrow++) {
                const int rr = rl + hrow * 8;
                const float2 xs = *(const float2*)&Xs[rr * 132 + c];
                const float2 vo = make_float2(xs.x + acc2[mt][nt][hrow*2]   + bv.x,
                                              xs.y + acc2[mt][nt][hrow*2+1] + bv.y);
                *(float2*)(X + (size_t)(m0 + rr) * 128 + c) = vo;
                *(float2*)&Xs[rr * 132 + c] = vo;
            }
        }

    // ---- phase 4 (fused qkv for layer d+1): LN1(Xs) -> A; 3 gemms -> g_qkv ----
    if (do_qkv) {
        __syncthreads();                          // Xs final; A free (last read ff1 i=3)
        ln_rows64(smem, Xs, ln1g_n, ln1b_n, tid);
        const __nv_bfloat16* wtn = g_wt + (size_t)(d + 1) * 196608;
        for (int nb = 0; nb < 3; nb++) {
            __syncthreads();                      // B free (prev gemm done)
            stage_B(smem + 17408, wtn + (size_t)nb * 16384, tid);
            __syncthreads();
            float acc[2][4][4] = {};
            gemm_64x128(acc, aBase, bBase);
#pragma unroll
            for (int mt = 0; mt < 2; mt++)
#pragma unroll
                for (int nt = 0; nt < 4; nt++) {
                    const int r = m0 + wm * 32 + mt * 16 + (lane >> 2);
                    const int c = nb * 128 + wn * 32 + nt * 8 + (lane & 3) * 2;
#pragma unroll
                    for (int hrow = 0; hrow < 2; hrow++)
                        *(__nv_bfloat162*)(g_qkv + (size_t)(r + hrow * 8) * 384 + c) =
                            __floats2bfloat162_rn(acc[mt][nt][hrow*2], acc[mt][nt][hrow*2+1]);
                }
        }
    }
}

// ---------------------------------------------------------------------------
// Local 3x3 attention: bf16 global traffic, fp32 smem compute. (unchanged)
// ---------------------------------------------------------------------------
__global__ __launch_bounds__(256) void k_attn()
{
    extern __shared__ float sm[];
    float* ksh = sm;              // 18*18*36
    float* vsh = sm + 11664;
    float* qo  = sm + 2 * 11664;  // 256*36
    const int tid = threadIdx.x;
    const int b   = blockIdx.z;
    const int ti0 = blockIdx.y * 16, tj0 = blockIdx.x * 16;
    const size_t img_base = (size_t)b * (SPATIAL * SPATIAL);

    for (int head = 0; head < 4; head++) {
        if (head) __syncthreads();
        const int qoff = head * 32, koff = 128 + head * 32, voff = 256 + head * 32;
        for (int idx = tid; idx < 18 * 18 * 16; idx += 256) {
            const int c2 = (idx & 15) * 2;
            const int rc = idx >> 4;
            const int r = rc / 18, cl = rc % 18;
            const int gi = ti0 + r - 1, gj = tj0 + cl - 1;
            float k0 = 0.f, k1 = 0.f, v0 = 0.f, v1 = 0.f;
            if (gi >= 0 && gi < SPATIAL && gj >= 0 && gj < SPATIAL) {
                const __nv_bfloat16* p = g_qkv + (img_base + (size_t)gi * SPATIAL + gj) * 384;
                const __nv_bfloat162 kp = *(const __nv_bfloat162*)(p + koff + c2);
                const __nv_bfloat162 vp = *(const __nv_bfloat162*)(p + voff + c2);
                k0 = __bfloat162float(kp.x); k1 = __bfloat162float(kp.y);
                v0 = __bfloat162float(vp.x); v1 = __bfloat162float(vp.y);
            }
            ksh[rc * 36 + c2] = k0; ksh[rc * 36 + c2 + 1] = k1;
            vsh[rc * 36 + c2] = v0; vsh[rc * 36 + c2 + 1] = v1;
        }
        for (int idx = tid; idx < 256 * 16; idx += 256) {
            const int c2 = (idx & 15) * 2, t = idx >> 4;
            const int gi = ti0 + (t >> 4), gj = tj0 + (t & 15);
            const __nv_bfloat162 qp = *(const __nv_bfloat162*)(
                g_qkv + (img_base + (size_t)gi * SPATIAL + gj) * 384 + qoff + c2);
            qo[t * 36 + c2] = __bfloat162float(qp.x);
            qo[t * 36 + c2 + 1] = __bfloat162float(qp.y);
        }
        __syncthreads();

        const int t = tid, lti = t >> 4, ltj = t & 15;
        float q[32];
#pragma unroll
        for (int i = 0; i < 8; i++) {
            float4 f = *(const float4*)&qo[t * 36 + i * 4];
            q[4*i+0]=f.x; q[4*i+1]=f.y; q[4*i+2]=f.z; q[4*i+3]=f.w;
        }
        float lg[9];
#pragma unroll
        for (int nb = 0; nb < 9; nb++) {
            const float* kp = &ksh[((lti + nb/3)*18 + (ltj + nb%3))*36];
            float dd = 0.f;
#pragma unroll
            for (int i = 0; i < 8; i++) {
                float4 f = *(const float4*)&kp[i*4];
                dd += q[4*i]*f.x + q[4*i+1]*f.y + q[4*i+2]*f.z + q[4*i+3]*f.w;
            }
            lg[nb] = dd * 0.17677669529663687f;
        }
        float mx = lg[0];
#pragma unroll
        for (int nb = 1; nb < 9; nb++) mx = fmaxf(mx, lg[nb]);
        float p9[9], Z = 0.f;
#pragma unroll
        for (int nb = 0; nb < 9; nb++) { p9[nb] = expf(lg[nb] - mx); Z += p9[nb]; }
        const float inv = 1.f / Z;
        float o[32] = {};
#pragma unroll
        for (int nb = 0; nb < 9; nb++) {
            const float wgt = p9[nb] * inv;
            const float* vp = &vsh[((lti + nb/3)*18 + (ltj + nb%3))*36];
#pragma unroll
            for (int i = 0; i < 8; i++) {
                float4 f = *(const float4*)&vp[i*4];
                o[4*i+0]+=wgt*f.x; o[4*i+1]+=wgt*f.y; o[4*i+2]+=wgt*f.z; o[4*i+3]+=wgt*f.w;
            }
        }
#pragma unroll
        for (int i = 0; i < 8; i++)
            *(float4*)&qo[t*36 + i*4] = make_float4(o[4*i], o[4*i+1], o[4*i+2], o[4*i+3]);
        __syncthreads();
        for (int idx = tid; idx < 256 * 16; idx += 256) {
            const int c2 = (idx & 15) * 2, tt = idx >> 4;
            const int gi = ti0 + (tt >> 4), gj = tj0 + (tt & 15);
            *(__nv_bfloat162*)(g_o + (img_base + (size_t)gi * SPATIAL + gj) * 128
                               + head * 32 + c2) =
                __floats2bfloat162_rn(qo[tt * 36 + c2], qo[tt * 36 + c2 + 1]);
        }
    }
}

// ---------------------------------------------------------------------------
extern "C" void kernel_launch(void* const* d_in, const int* in_sizes, int n_in,
                              void* d_out, int out_size)
{
    (void)in_sizes; (void)n_in; (void)out_size;
    const float* x_in  = (const float*)d_in[0];
    const float* ln1_g = (const float*)d_in[1];
    const float* ln1_b = (const float*)d_in[2];
    const float* qkv_w = (const float*)d_in[3];
    const float* out_w = (const float*)d_in[4];
    const float* out_b = (const float*)d_in[5];
    const float* ln2_g = (const float*)d_in[6];
    const float* ln2_b = (const float*)d_in[7];
    const float* ff_w1 = (const float*)d_in[8];
    const float* ff_b1 = (const float*)d_in[9];
    const float* ff_w2 = (const float*)d_in[10];
    const float* ff_b2 = (const float*)d_in[11];
    float* X = (float*)d_out;

    const int SM_QKV   = 52224;
    const int SM_FUSED = 103424;
    const int SM_ATTN  = (2 * 11664 + 9216) * 4;
    cudaFuncSetAttribute(k_qkv,   cudaFuncAttributeMaxDynamicSharedMemorySize, SM_QKV);
    cudaFuncSetAttribute(k_fused, cudaFuncAttributeMaxDynamicSharedMemorySize, SM_FUSED);
    cudaFuncSetAttribute(k_attn,  cudaFuncAttributeMaxDynamicSharedMemorySize, SM_ATTN);

    cudaMemcpyAsync(X, x_in, (size_t)MTOT * 128 * sizeof(float),
                    cudaMemcpyDeviceToDevice, 0);
    k_prep<<<3072, 256>>>(qkv_w, out_w, ff_w1, ff_w2);

    const int GB = MTOT / 64;    // 2048 CTAs
    dim3 gAttn(8, 8, 8);
    k_qkv<<<GB, 256, SM_QKV>>>(X, ln1_g, ln1_b, 0);   // layer 0 qkv
    for (int d = 0; d < 4; d++) {
        const int dn = (d + 1) & 3;
        k_attn<<<gAttn, 256, SM_ATTN>>>();
        k_fused<<<GB, 256, SM_FUSED>>>(out_b + d*128, ln2_g + d*128, ln2_b + d*128,
                                       ff_b1 + d*512, ff_b2 + d*128, X, d,
                                       ln1_g + dn*128, ln1_b + dn*128, (d < 3) ? 1 : 0);
    }
}

// round 15
// speedup vs baseline: 1.3126x; 1.2357x over previous
#include <cuda_runtime.h>
#include <cuda_bf16.h>
#include <math.h>
#include <stdint.h>

#define MTOT 131072
#define SPATIAL 128

__device__ __align__(256) __nv_bfloat16 g_qkv[(size_t)MTOT * 384];
__device__ __align__(256) __nv_bfloat16 g_o  [(size_t)MTOT * 128];
__device__ __align__(256) __nv_bfloat16 g_wt [786432];  // 4 layers x 12 images x [128n][128k]

__device__ __forceinline__ float gelu_exact(float a) {
    return 0.5f * a * (1.0f + erff(a * 0.70710678118654752440f));
}

__device__ __forceinline__ uint32_t smem_u32(const void* p) {
    uint32_t a;
    asm("{ .reg .u64 t; cvta.to.shared.u64 t, %1; cvt.u32.u64 %0, t; }" : "=r"(a) : "l"(p));
    return a;
}

#define LDSM4(r0, r1, r2, r3, addr) \
    asm volatile("ldmatrix.sync.aligned.m8n8.x4.shared.b16 {%0,%1,%2,%3}, [%4];" \
                 : "=r"(r0), "=r"(r1), "=r"(r2), "=r"(r3) : "r"(addr))

#define MMA16816(d, a, b) \
    asm volatile("mma.sync.aligned.m16n8k16.row.col.f32.bf16.bf16.f32 " \
                 "{%0,%1,%2,%3},{%4,%5,%6,%7},{%8,%9},{%0,%1,%2,%3};" \
                 : "+f"((d)[0]), "+f"((d)[1]), "+f"((d)[2]), "+f"((d)[3]) \
                 : "r"((a)[0]), "r"((a)[1]), "r"((a)[2]), "r"((a)[3]), \
                   "r"((b)[0]), "r"((b)[1]))

// ---------------------------------------------------------------------------
// Prep: transpose weights to n-major/k-contig bf16 images [128n][128k].
// Per layer (12 imgs): 0-2 qkv n-blocks, 3 proj, 4-7 ff1 n-blocks, 8-11 ff2 k-chunks.
// ---------------------------------------------------------------------------
__global__ __launch_bounds__(256) void k_prep(
    const float* __restrict__ qkv_w, const float* __restrict__ out_w,
    const float* __restrict__ ff_w1, const float* __restrict__ ff_w2)
{
    const int idx = blockIdx.x * 256 + threadIdx.x;   // 0..786431
    const int d   = idx / 196608;
    const int rem = idx % 196608;
    const int img = rem / 16384;
    const int pos = rem % 16384;
    const int n = pos >> 7, k = pos & 127;
    float val;
    if (img < 3)       val = qkv_w[(size_t)(d * 128 + k) * 384 + img * 128 + n];
    else if (img == 3) val = out_w[(size_t)(d * 128 + k) * 128 + n];
    else if (img < 8)  val = ff_w1[(size_t)(d * 128 + k) * 512 + (img - 4) * 128 + n];
    else               val = ff_w2[(size_t)(d * 512 + (img - 8) * 128 + k) * 128 + n];
    g_wt[idx] = __float2bfloat16(val);
}

// ---------------------------------------------------------------------------
// Shared helpers. Warp tile 32x32 (2 mt x 4 nt of m16n8k16), row stride 272 B.
// ---------------------------------------------------------------------------
__device__ __forceinline__ void stage_B(char* bs, const __nv_bfloat16* img, int tid) {
    const uint4* s4 = (const uint4*)img;
#pragma unroll
    for (int i = 0; i < 8; i++) {
        const int u = tid + i * 256;            // 2048 x 16B
        const int row = u >> 4, c8 = u & 15;
        *(uint4*)(bs + (size_t)row * 272 + c8 * 16) = s4[u];
    }
}

__device__ __forceinline__ void gemm_64x128(
    float acc[2][4][4], uint32_t aBase, uint32_t bBase)
{
#pragma unroll
    for (int kk = 0; kk < 8; kk++) {
        uint32_t a[2][4];
#pragma unroll
        for (int mt = 0; mt < 2; mt++)
            LDSM4(a[mt][0], a[mt][1], a[mt][2], a[mt][3],
                  aBase + (uint32_t)(mt * 16 * 272 + kk * 32));
        uint32_t b[4][2];
#pragma unroll
        for (int nt2 = 0; nt2 < 2; nt2++)
            LDSM4(b[nt2*2][0], b[nt2*2][1], b[nt2*2+1][0], b[nt2*2+1][1],
                  bBase + (uint32_t)(nt2 * 16 * 272 + kk * 32));
#pragma unroll
        for (int mt = 0; mt < 2; mt++)
#pragma unroll
            for (int nt = 0; nt < 4; nt++)
                MMA16816(acc[mt][nt], a[mt], b[nt]);
    }
}

// LayerNorm of 64 rows from a fp32 smem tile (stride 132) -> bf16 A tile (stride 272).
__device__ __forceinline__ void ln_rows64(
    char* smem, const float* Xs, const float* g, const float* b, int tid)
{
    const int m = tid >> 2, q = tid & 3;
    const float* xp = &Xs[m * 132 + q * 32];
    float4 v[8];
#pragma unroll
    for (int j = 0; j < 8; j++) v[j] = ((const float4*)xp)[j];
    float s = 0.f, sq = 0.f;
#pragma unroll
    for (int j = 0; j < 8; j++) {
        s  += v[j].x + v[j].y + v[j].z + v[j].w;
        sq += v[j].x*v[j].x + v[j].y*v[j].y + v[j].z*v[j].z + v[j].w*v[j].w;
    }
    s  += __shfl_xor_sync(0xffffffffu, s , 1);
    sq += __shfl_xor_sync(0xffffffffu, sq, 1);
    s  += __shfl_xor_sync(0xffffffffu, s , 2);
    sq += __shfl_xor_sync(0xffffffffu, sq, 2);
    const float mean = s * (1.f / 128.f);
    const float rstd = rsqrtf(sq * (1.f / 128.f) - mean * mean + 1e-3f);
    char* arow = smem + (size_t)m * 272 + q * 64;
#pragma unroll
    for (int j = 0; j < 4; j++) {
        const int k = q * 32 + j * 8;
        const float4 f0 = v[2*j], f1 = v[2*j+1];
        const float4 g0 = *(const float4*)(g + k);
        const float4 g1 = *(const float4*)(g + k + 4);
        const float4 c0 = *(const float4*)(b + k);
        const float4 c1 = *(const float4*)(b + k + 4);
        __nv_bfloat16 t8[8];
        t8[0]=__float2bfloat16((f0.x-mean)*rstd*g0.x+c0.x);
        t8[1]=__float2bfloat16((f0.y-mean)*rstd*g0.y+c0.y);
        t8[2]=__float2bfloat16((f0.z-mean)*rstd*g0.z+c0.z);
        t8[3]=__float2bfloat16((f0.w-mean)*rstd*g0.w+c0.w);
        t8[4]=__float2bfloat16((f1.x-mean)*rstd*g1.x+c1.x);
        t8[5]=__float2bfloat16((f1.y-mean)*rstd*g1.y+c1.y);
        t8[6]=__float2bfloat16((f1.z-mean)*rstd*g1.z+c1.z);
        t8[7]=__float2bfloat16((f1.w-mean)*rstd*g1.w+c1.w);
        *(uint4*)(arow + j * 16) = *(const uint4*)t8;
    }
}

// ---------------------------------------------------------------------------
// Kernel 1 (layer 0 only): y = LN1(x); qkv = y @ Wqkv -> g_qkv bf16.
// ---------------------------------------------------------------------------
__global__ void __launch_bounds__(256, 3) k_qkv(
    const float* __restrict__ X, const float* __restrict__ gamma,
    const float* __restrict__ beta, int d)
{
    extern __shared__ char smem[];
    const uint32_t sbA = smem_u32(smem);
    const uint32_t sbB = sbA + 17408;
    const int tid = threadIdx.x, wid = tid >> 5, lane = tid & 31;
    const int wm = wid >> 2, wn = wid & 3;
    const int m0 = blockIdx.x * 64;
    const __nv_bfloat16* wt = g_wt + (size_t)d * 196608;

    const uint32_t aBase = sbA + (uint32_t)((wm * 32 + (lane & 15)) * 272 + (lane >> 4) * 16);
    const uint32_t bBase = sbB + (uint32_t)((wn * 32 + ((lane >> 4) * 8) + (lane & 7)) * 272
                                            + ((lane >> 3) & 1) * 16);

    {   // stage A: LN1(x) from GLOBAL fp32 x
        const int m = tid >> 2, q = tid & 3;
        const float* ap = X + (size_t)(m0 + m) * 128 + q * 32;
        float4 v[8];
#pragma unroll
        for (int j = 0; j < 8; j++) v[j] = ((const float4*)ap)[j];
        float s = 0.f, sq = 0.f;
#pragma unroll
        for (int j = 0; j < 8; j++) {
            s  += v[j].x + v[j].y + v[j].z + v[j].w;
            sq += v[j].x*v[j].x + v[j].y*v[j].y + v[j].z*v[j].z + v[j].w*v[j].w;
        }
        s  += __shfl_xor_sync(0xffffffffu, s , 1);
        sq += __shfl_xor_sync(0xffffffffu, sq, 1);
        s  += __shfl_xor_sync(0xffffffffu, s , 2);
        sq += __shfl_xor_sync(0xffffffffu, sq, 2);
        const float mean = s * (1.f / 128.f);
        const float rstd = rsqrtf(sq * (1.f / 128.f) - mean * mean + 1e-3f);
        char* arow = smem + (size_t)m * 272 + q * 64;
#pragma unroll
        for (int j = 0; j < 4; j++) {
            const int k = q * 32 + j * 8;
            const float4 f0 = v[2*j], f1 = v[2*j+1];
            const float4 g0 = *(const float4*)(gamma + k);
            const float4 g1 = *(const float4*)(gamma + k + 4);
            const float4 b0 = *(const float4*)(beta + k);
            const float4 b1 = *(const float4*)(beta + k + 4);
            __nv_bfloat16 t8[8];
            t8[0]=__float2bfloat16((f0.x-mean)*rstd*g0.x+b0.x);
            t8[1]=__float2bfloat16((f0.y-mean)*rstd*g0.y+b0.y);
            t8[2]=__float2bfloat16((f0.z-mean)*rstd*g0.z+b0.z);
            t8[3]=__float2bfloat16((f0.w-mean)*rstd*g0.w+b0.w);
            t8[4]=__float2bfloat16((f1.x-mean)*rstd*g1.x+b1.x);
            t8[5]=__float2bfloat16((f1.y-mean)*rstd*g1.y+b1.y);
            t8[6]=__float2bfloat16((f1.z-mean)*rstd*g1.z+b1.z);
            t8[7]=__float2bfloat16((f1.w-mean)*rstd*g1.w+b1.w);
            *(uint4*)(arow + j * 16) = *(const uint4*)t8;
        }
    }

    for (int nb = 0; nb < 3; nb++) {
        if (nb) __syncthreads();
        stage_B(smem + 17408, wt + (size_t)nb * 16384, tid);
        __syncthreads();
        float acc[2][4][4] = {};
        gemm_64x128(acc, aBase, bBase);
#pragma unroll
        for (int mt = 0; mt < 2; mt++)
#pragma unroll
            for (int nt = 0; nt < 4; nt++) {
                const int r = m0 + wm * 32 + mt * 16 + (lane >> 2);
                const int c = nb * 128 + wn * 32 + nt * 8 + (lane & 3) * 2;
#pragma unroll
                for (int hrow = 0; hrow < 2; hrow++)
                    *(__nv_bfloat162*)(g_qkv + (size_t)(r + hrow * 8) * 384 + c) =
                        __floats2bfloat162_rn(acc[mt][nt][hrow*2], acc[mt][nt][hrow*2+1]);
            }
    }
}

// ---------------------------------------------------------------------------
// FUSED: x += o@Wp + bp; y = LN2(x); h_i = gelu(y@W1_i+b1_i); x += sum h_i@W2_i + b2;
// then (do_qkv) LN1_next(x) and qkv GEMMs for layer d+1 straight from smem Xs.
// CTA = 64 tokens, 256 threads (8 warps 2Mx4N).
// smem: A 17408 @0, B 34816 @17408, H 17408 @52224, Xs fp32 64x132 @69632.
// Total 103424 B -> 2 CTAs/SM.
// ---------------------------------------------------------------------------
__global__ void __launch_bounds__(256, 2) k_fused(
    const float* __restrict__ bp, const float* __restrict__ ln2_g,
    const float* __restrict__ ln2_b, const float* __restrict__ b1,
    const float* __restrict__ b2, float* __restrict__ X, int d,
    const float* __restrict__ ln1g_n, const float* __restrict__ ln1b_n, int do_qkv)
{
    extern __shared__ char smem[];
    const uint32_t sbA = smem_u32(smem);
    const uint32_t sbB = sbA + 17408;
    const uint32_t sbH = sbA + 52224;
    float* Xs = (float*)(smem + 69632);              // [64][132] fp32
    const int tid = threadIdx.x, wid = tid >> 5, lane = tid & 31;
    const int wm = wid >> 2, wn = wid & 3;
    const int m0 = blockIdx.x * 64;
    const __nv_bfloat16* wt = g_wt + (size_t)d * 196608;

    const uint32_t lA = (uint32_t)((wm * 32 + (lane & 15)) * 272 + (lane >> 4) * 16);
    const uint32_t aBase = sbA + lA;
    const uint32_t hBase = sbH + lA;
    const uint32_t bBase = sbB + (uint32_t)((wn * 32 + ((lane >> 4) * 8) + (lane & 7)) * 272
                                            + ((lane >> 3) & 1) * 16);

    // ---- phase 1: proj ----
    {
        const int m = tid >> 2, q = tid & 3;
        const __nv_bfloat16* ap = g_o + (size_t)(m0 + m) * 128 + q * 32;
        char* arow = smem + (size_t)m * 272 + q * 64;
#pragma unroll
        for (int j = 0; j < 4; j++)
            *(uint4*)(arow + j * 16) = ((const uint4*)ap)[j];
        stage_B(smem + 17408, wt + 3 * 16384, tid);
    }
    __syncthreads();
    {
        float acc[2][4][4] = {};
        gemm_64x128(acc, aBase, bBase);
#pragma unroll
        for (int mt = 0; mt < 2; mt++)
#pragma unroll
            for (int nt = 0; nt < 4; nt++) {
                const int rl = wm * 32 + mt * 16 + (lane >> 2);
                const int c  = wn * 32 + nt * 8 + (lane & 3) * 2;
                const float2 bv = *(const float2*)(bp + c);
#pragma unroll
                for (int hrow = 0; hrow < 2; hrow++) {
                    const int rr = rl + hrow * 8;
                    const float2 xo = *(const float2*)(X + (size_t)(m0 + rr) * 128 + c);
                    *(float2*)&Xs[rr * 132 + c] = make_float2(
                        xo.x + acc[mt][nt][hrow*2]   + bv.x,
                        xo.y + acc[mt][nt][hrow*2+1] + bv.y);
                }
            }
    }
    __syncthreads();

    // ---- phase 2: LN2 from Xs -> A ----
    ln_rows64(smem, Xs, ln2_g, ln2_b, tid);

    // ---- phase 3: interleaved ff1/ff2 over 4 128-col chunks ----
    float acc2[2][4][4] = {};
    for (int i = 0; i < 4; i++) {
        __syncthreads();                          // B/H safe to overwrite
        stage_B(smem + 17408, wt + (size_t)(4 + i) * 16384, tid);
        __syncthreads();
        {   // h_i = gelu(y @ W1_i + b1_i) -> H smem (bf16)
            float acc[2][4][4] = {};
            gemm_64x128(acc, aBase, bBase);
#pragma unroll
            for (int mt = 0; mt < 2; mt++)
#pragma unroll
                for (int nt = 0; nt < 4; nt++) {
                    const int rl = wm * 32 + mt * 16 + (lane >> 2);
                    const int c  = wn * 32 + nt * 8 + (lane & 3) * 2;
                    const float2 bv = *(const float2*)(b1 + i * 128 + c);
#pragma unroll
                    for (int hrow = 0; hrow < 2; hrow++) {
                        const int rr = rl + hrow * 8;
                        *(__nv_bfloat162*)(smem + 52224 + (size_t)rr * 272 + c * 2) =
                            __floats2bfloat162_rn(gelu_exact(acc[mt][nt][hrow*2]   + bv.x),
                                                  gelu_exact(acc[mt][nt][hrow*2+1] + bv.y));
                    }
                }
        }
        __syncthreads();                          // H ready; B readers done
        stage_B(smem + 17408, wt + (size_t)(8 + i) * 16384, tid);
        __syncthreads();
        gemm_64x128(acc2, hBase, bBase);          // acc2 += h_i @ W2_i
    }

    // ---- final epilogue: X = Xs + acc2 + b2 (global + back into Xs) ----
#pragma unroll
    for (int mt = 0; mt < 2; mt++)
#pragma unroll
        for (int nt = 0; nt < 4; nt++) {
            const int rl = wm * 32 + mt * 16 + (lane >> 2);
            const int c  = wn * 32 + nt * 8 + (lane & 3) * 2;
            const float2 bv = *(const float2*)(b2 + c);
#pragma unroll
            for (int hrow = 0; hrow < 2; hrow++) {
                const int rr = rl + hrow * 8;
                const float2 xs = *(const float2*)&Xs[rr * 132 + c];
                const float2 vo = make_float2(xs.x + acc2[mt][nt][hrow*2]   + bv.x,
                                              xs.y + acc2[mt][nt][hrow*2+1] + bv.y);
                *(float2*)(X + (size_t)(m0 + rr) * 128 + c) = vo;
                *(float2*)&Xs[rr * 132 + c] = vo;
            }
        }

    // ---- phase 4 (fused qkv for layer d+1): LN1(Xs) -> A; 3 gemms -> g_qkv ----
    if (do_qkv) {
        __syncthreads();                          // Xs final; A free
        ln_rows64(smem, Xs, ln1g_n, ln1b_n, tid);
        const __nv_bfloat16* wtn = g_wt + (size_t)(d + 1) * 196608;
        for (int nb = 0; nb < 3; nb++) {
            __syncthreads();                      // B free (prev gemm done)
            stage_B(smem + 17408, wtn + (size_t)nb * 16384, tid);
            __syncthreads();
            float acc[2][4][4] = {};
            gemm_64x128(acc, aBase, bBase);
#pragma unroll
            for (int mt = 0; mt < 2; mt++)
#pragma unroll
                for (int nt = 0; nt < 4; nt++) {
                    const int r = m0 + wm * 32 + mt * 16 + (lane >> 2);
                    const int c = nb * 128 + wn * 32 + nt * 8 + (lane & 3) * 2;
#pragma unroll
                    for (int hrow = 0; hrow < 2; hrow++)
                        *(__nv_bfloat162*)(g_qkv + (size_t)(r + hrow * 8) * 384 + c) =
                            __floats2bfloat162_rn(acc[mt][nt][hrow*2], acc[mt][nt][hrow*2+1]);
                }
        }
    }
}

// ---------------------------------------------------------------------------
// Local 3x3 attention, REWRITTEN:
//  - K/V halo stored as raw bf16 in smem, row stride 40 bf16 (80 B):
//    LDS.128 8-lane phases hit distinct 16B sub-banks -> conflict-free.
//  - q loaded global->regs directly (4x uint4 / 64 B contiguous per thread);
//    o stored regs->global directly. No q/o smem staging, smem = 51840 B.
// ---------------------------------------------------------------------------
#define HP 40   // halo row pitch in bf16 elements

__global__ __launch_bounds__(256) void k_attn()
{
    extern __shared__ __nv_bfloat16 sm16[];
    __nv_bfloat16* ksh = sm16;                 // 324 x HP
    __nv_bfloat16* vsh = sm16 + 324 * HP;
    const int tid = threadIdx.x;
    const int b   = blockIdx.z;
    const int ti0 = blockIdx.y * 16, tj0 = blockIdx.x * 16;
    const size_t img_base = (size_t)b * (SPATIAL * SPATIAL);
    const int lti = tid >> 4, ltj = tid & 15;
    const size_t my_tok = img_base + (size_t)(ti0 + lti) * SPATIAL + (tj0 + ltj);

    for (int head = 0; head < 4; head++) {
        if (head) __syncthreads();             // prev head's reads done
        const int qoff = head * 32, koff = 128 + head * 32, voff = 256 + head * 32;

        // ---- stage halo K/V as bf16 (uint4 granularity, zero-padded) ----
        for (int u = tid; u < 324 * 4; u += 256) {
            const int rc = u >> 2, c8 = u & 3;
            const int r = rc / 18, cl = rc % 18;
            const int gi = ti0 + r - 1, gj = tj0 + cl - 1;
            uint4 kv = make_uint4(0, 0, 0, 0), vv = make_uint4(0, 0, 0, 0);
            if (gi >= 0 && gi < SPATIAL && gj >= 0 && gj < SPATIAL) {
                const __nv_bfloat16* p = g_qkv + (img_base + (size_t)gi * SPATIAL + gj) * 384;
                kv = *(const uint4*)(p + koff + c8 * 8);
                vv = *(const uint4*)(p + voff + c8 * 8);
            }
            *(uint4*)(ksh + rc * HP + c8 * 8) = kv;
            *(uint4*)(vsh + rc * HP + c8 * 8) = vv;
        }
        // ---- q: direct global -> regs ----
        float q[32];
        {
            const __nv_bfloat16* qp = g_qkv + my_tok * 384 + qoff;
#pragma unroll
            for (int j = 0; j < 4; j++) {
                const uint4 u4 = *(const uint4*)(qp + j * 8);
                const uint32_t* w = (const uint32_t*)&u4;
#pragma unroll
                for (int h2 = 0; h2 < 4; h2++) {
                    const float2 f = __bfloat1622float2(*(const __nv_bfloat162*)&w[h2]);
                    q[j*8 + h2*2] = f.x; q[j*8 + h2*2 + 1] = f.y;
                }
            }
        }
        __syncthreads();                       // halo ready

        // ---- logits ----
        float lg[9];
#pragma unroll
        for (int nb = 0; nb < 9; nb++) {
            const __nv_bfloat16* kp = ksh + ((lti + nb/3) * 18 + (ltj + nb%3)) * HP;
            float dd = 0.f;
#pragma unroll
            for (int j = 0; j < 4; j++) {
                const uint4 u4 = *(const uint4*)(kp + j * 8);
                const uint32_t* w = (const uint32_t*)&u4;
#pragma unroll
                for (int h2 = 0; h2 < 4; h2++) {
                    const float2 f = __bfloat1622float2(*(const __nv_bfloat162*)&w[h2]);
                    dd += q[j*8 + h2*2] * f.x + q[j*8 + h2*2 + 1] * f.y;
                }
            }
            lg[nb] = dd * 0.17677669529663687f;
        }
        float mx = lg[0];
#pragma unroll
        for (int nb = 1; nb < 9; nb++) mx = fmaxf(mx, lg[nb]);
        float p9[9], Z = 0.f;
#pragma unroll
        for (int nb = 0; nb < 9; nb++) { p9[nb] = expf(lg[nb] - mx); Z += p9[nb]; }
        const float inv = 1.f / Z;

        // ---- weighted V sum ----
        float o[32] = {};
#pragma unroll
        for (int nb = 0; nb < 9; nb++) {
            const float wgt = p9[nb] * inv;
            const __nv_bfloat16* vp = vsh + ((lti + nb/3) * 18 + (ltj + nb%3)) * HP;
#pragma unroll
            for (int j = 0; j < 4; j++) {
                const uint4 u4 = *(const uint4*)(vp + j * 8);
                const uint32_t* w = (const uint32_t*)&u4;
#pragma unroll
                for (int h2 = 0; h2 < 4; h2++) {
                    const float2 f = __bfloat1622float2(*(const __nv_bfloat162*)&w[h2]);
                    o[j*8 + h2*2]     += wgt * f.x;
                    o[j*8 + h2*2 + 1] += wgt * f.y;
                }
            }
        }

        // ---- o: direct regs -> global (64 B contiguous per thread) ----
        {
            __nv_bfloat16* op = g_o + my_tok * 128 + head * 32;
#pragma unroll
            for (int j = 0; j < 4; j++) {
                uint4 u4;
                uint32_t* w = (uint32_t*)&u4;
#pragma unroll
                for (int h2 = 0; h2 < 4; h2++) {
                    const __nv_bfloat162 bb = __floats2bfloat162_rn(
                        o[j*8 + h2*2], o[j*8 + h2*2 + 1]);
                    w[h2] = *(const uint32_t*)&bb;
                }
                *(uint4*)(op + j * 8) = u4;
            }
        }
    }
}

// ---------------------------------------------------------------------------
extern "C" void kernel_launch(void* const* d_in, const int* in_sizes, int n_in,
                              void* d_out, int out_size)
{
    (void)in_sizes; (void)n_in; (void)out_size;
    const float* x_in  = (const float*)d_in[0];
    const float* ln1_g = (const float*)d_in[1];
    const float* ln1_b = (const float*)d_in[2];
    const float* qkv_w = (const float*)d_in[3];
    const float* out_w = (const float*)d_in[4];
    const float* out_b = (const float*)d_in[5];
    const float* ln2_g = (const float*)d_in[6];
    const float* ln2_b = (const float*)d_in[7];
    const float* ff_w1 = (const float*)d_in[8];
    const float* ff_b1 = (const float*)d_in[9];
    const float* ff_w2 = (const float*)d_in[10];
    const float* ff_b2 = (const float*)d_in[11];
    float* X = (float*)d_out;

    const int SM_QKV   = 52224;
    const int SM_FUSED = 103424;
    const int SM_ATTN  = 324 * HP * 2 * 2;      // 51840 B
    cudaFuncSetAttribute(k_qkv,   cudaFuncAttributeMaxDynamicSharedMemorySize, SM_QKV);
    cudaFuncSetAttribute(k_fused, cudaFuncAttributeMaxDynamicSharedMemorySize, SM_FUSED);
    cudaFuncSetAttribute(k_attn,  cudaFuncAttributeMaxDynamicSharedMemorySize, SM_ATTN);

    cudaMemcpyAsync(X, x_in, (size_t)MTOT * 128 * sizeof(float),
                    cudaMemcpyDeviceToDevice, 0);
    k_prep<<<3072, 256>>>(qkv_w, out_w, ff_w1, ff_w2);

    const int GB = MTOT / 64;    // 2048 CTAs
    dim3 gAttn(8, 8, 8);
    k_qkv<<<GB, 256, SM_QKV>>>(X, ln1_g, ln1_b, 0);   // layer 0 qkv
    for (int d = 0; d < 4; d++) {
        const int dn = (d + 1) & 3;
        k_attn<<<gAttn, 256, SM_ATTN>>>();
        k_fused<<<GB, 256, SM_FUSED>>>(out_b + d*128, ln2_g + d*128, ln2_b + d*128,
                                       ff_b1 + d*512, ff_b2 + d*128, X, d,
                                       ln1_g + dn*128, ln1_b + dn*128, (d < 3) ? 1 : 0);
    }
}

// round 16
// speedup vs baseline: 1.3463x; 1.0256x over previous
#include <cuda_runtime.h>
#include <cuda_bf16.h>
#include <math.h>
#include <stdint.h>

#define MTOT 131072
#define SPATIAL 128

__device__ __align__(256) __nv_bfloat16 g_qkv[(size_t)MTOT * 384];
__device__ __align__(256) __nv_bfloat16 g_o  [(size_t)MTOT * 128];
__device__ __align__(256) __nv_bfloat16 g_wt [786432];  // 4 layers x 12 images x [128n][128k]

__device__ __forceinline__ float gelu_exact(float a) {
    return 0.5f * a * (1.0f + erff(a * 0.70710678118654752440f));
}

__device__ __forceinline__ uint32_t smem_u32(const void* p) {
    uint32_t a;
    asm("{ .reg .u64 t; cvta.to.shared.u64 t, %1; cvt.u32.u64 %0, t; }" : "=r"(a) : "l"(p));
    return a;
}

#define LDSM4(r0, r1, r2, r3, addr) \
    asm volatile("ldmatrix.sync.aligned.m8n8.x4.shared.b16 {%0,%1,%2,%3}, [%4];" \
                 : "=r"(r0), "=r"(r1), "=r"(r2), "=r"(r3) : "r"(addr))

#define MMA16816(d, a, b) \
    asm volatile("mma.sync.aligned.m16n8k16.row.col.f32.bf16.bf16.f32 " \
                 "{%0,%1,%2,%3},{%4,%5,%6,%7},{%8,%9},{%0,%1,%2,%3};" \
                 : "+f"((d)[0]), "+f"((d)[1]), "+f"((d)[2]), "+f"((d)[3]) \
                 : "r"((a)[0]), "r"((a)[1]), "r"((a)[2]), "r"((a)[3]), \
                   "r"((b)[0]), "r"((b)[1]))

// ---------------------------------------------------------------------------
// Prep: transpose weights to n-major/k-contig bf16 images [128n][128k].
// Per layer (12 imgs): 0-2 qkv n-blocks, 3 proj, 4-7 ff1 n-blocks, 8-11 ff2 k-chunks.
// ---------------------------------------------------------------------------
__global__ __launch_bounds__(256) void k_prep(
    const float* __restrict__ qkv_w, const float* __restrict__ out_w,
    const float* __restrict__ ff_w1, const float* __restrict__ ff_w2)
{
    const int idx = blockIdx.x * 256 + threadIdx.x;   // 0..786431
    const int d   = idx / 196608;
    const int rem = idx % 196608;
    const int img = rem / 16384;
    const int pos = rem % 16384;
    const int n = pos >> 7, k = pos & 127;
    float val;
    if (img < 3)       val = qkv_w[(size_t)(d * 128 + k) * 384 + img * 128 + n];
    else if (img == 3) val = out_w[(size_t)(d * 128 + k) * 128 + n];
    else if (img < 8)  val = ff_w1[(size_t)(d * 128 + k) * 512 + (img - 4) * 128 + n];
    else               val = ff_w2[(size_t)(d * 512 + (img - 8) * 128 + k) * 128 + n];
    g_wt[idx] = __float2bfloat16(val);
}

// ---------------------------------------------------------------------------
// Shared helpers. Row stride 272 B -> conflict-free ldmatrix.
// ---------------------------------------------------------------------------
__device__ __forceinline__ void stage_B(char* bs, const __nv_bfloat16* img, int tid) {
    const uint4* s4 = (const uint4*)img;
#pragma unroll
    for (int i = 0; i < 8; i++) {
        const int u = tid + i * 256;            // 2048 x 16B
        const int row = u >> 4, c8 = u & 15;
        *(uint4*)(bs + (size_t)row * 272 + c8 * 16) = s4[u];
    }
}

// Warp tile 32x32 (used by standalone k_qkv)
__device__ __forceinline__ void gemm_64x128(
    float acc[2][4][4], uint32_t aBase, uint32_t bBase)
{
#pragma unroll
    for (int kk = 0; kk < 8; kk++) {
        uint32_t a[2][4];
#pragma unroll
        for (int mt = 0; mt < 2; mt++)
            LDSM4(a[mt][0], a[mt][1], a[mt][2], a[mt][3],
                  aBase + (uint32_t)(mt * 16 * 272 + kk * 32));
        uint32_t b[4][2];
#pragma unroll
        for (int nt2 = 0; nt2 < 2; nt2++)
            LDSM4(b[nt2*2][0], b[nt2*2][1], b[nt2*2+1][0], b[nt2*2+1][1],
                  bBase + (uint32_t)(nt2 * 16 * 272 + kk * 32));
#pragma unroll
        for (int mt = 0; mt < 2; mt++)
#pragma unroll
            for (int nt = 0; nt < 4; nt++)
                MMA16816(acc[mt][nt], a[mt], b[nt]);
    }
}

// Warp tile 64x32 (fused kernel): 6 ldsm per 16 mma (crossbar ratio 0.375).
__device__ __forceinline__ void gemm_128x128(
    float acc[4][4][4], uint32_t aBase, uint32_t bBase)
{
#pragma unroll
    for (int kk = 0; kk < 8; kk++) {
        uint32_t a[4][4];
#pragma unroll
        for (int mt = 0; mt < 4; mt++)
            LDSM4(a[mt][0], a[mt][1], a[mt][2], a[mt][3],
                  aBase + (uint32_t)(mt * 16 * 272 + kk * 32));
        uint32_t b[4][2];
#pragma unroll
        for (int nt2 = 0; nt2 < 2; nt2++)
            LDSM4(b[nt2*2][0], b[nt2*2][1], b[nt2*2+1][0], b[nt2*2+1][1],
                  bBase + (uint32_t)(nt2 * 16 * 272 + kk * 32));
#pragma unroll
        for (int mt = 0; mt < 4; mt++)
#pragma unroll
            for (int nt = 0; nt < 4; nt++)
                MMA16816(acc[mt][nt], a[mt], b[nt]);
    }
}

// LayerNorm of 128 rows from fp32 smem tile (stride 132) -> bf16 A tile (stride 272).
// 256 threads: 2 threads per row, 64 cols each.
__device__ __forceinline__ void ln_rows128(
    char* smem, const float* Xs, const float* g, const float* b, int tid)
{
    const int m = tid >> 1, h = tid & 1;
    const float* xp = &Xs[m * 132 + h * 64];
    float4 v[16];
#pragma unroll
    for (int j = 0; j < 16; j++) v[j] = ((const float4*)xp)[j];
    float s = 0.f, sq = 0.f;
#pragma unroll
    for (int j = 0; j < 16; j++) {
        s  += v[j].x + v[j].y + v[j].z + v[j].w;
        sq += v[j].x*v[j].x + v[j].y*v[j].y + v[j].z*v[j].z + v[j].w*v[j].w;
    }
    s  += __shfl_xor_sync(0xffffffffu, s , 1);
    sq += __shfl_xor_sync(0xffffffffu, sq, 1);
    const float mean = s * (1.f / 128.f);
    const float rstd = rsqrtf(sq * (1.f / 128.f) - mean * mean + 1e-3f);
    char* arow = smem + (size_t)m * 272 + h * 128;
#pragma unroll
    for (int j = 0; j < 8; j++) {
        const int k = h * 64 + j * 8;
        const float4 f0 = v[2*j], f1 = v[2*j+1];
        const float4 g0 = *(const float4*)(g + k);
        const float4 g1 = *(const float4*)(g + k + 4);
        const float4 c0 = *(const float4*)(b + k);
        const float4 c1 = *(const float4*)(b + k + 4);
        __nv_bfloat16 t8[8];
        t8[0]=__float2bfloat16((f0.x-mean)*rstd*g0.x+c0.x);
        t8[1]=__float2bfloat16((f0.y-mean)*rstd*g0.y+c0.y);
        t8[2]=__float2bfloat16((f0.z-mean)*rstd*g0.z+c0.z);
        t8[3]=__float2bfloat16((f0.w-mean)*rstd*g0.w+c0.w);
        t8[4]=__float2bfloat16((f1.x-mean)*rstd*g1.x+c1.x);
        t8[5]=__float2bfloat16((f1.y-mean)*rstd*g1.y+c1.y);
        t8[6]=__float2bfloat16((f1.z-mean)*rstd*g1.z+c1.z);
        t8[7]=__float2bfloat16((f1.w-mean)*rstd*g1.w+c1.w);
        *(uint4*)(arow + j * 16) = *(const uint4*)t8;
    }
}

// ---------------------------------------------------------------------------
// Kernel 1 (layer 0 only): y = LN1(x); qkv = y @ Wqkv -> g_qkv bf16.
// ---------------------------------------------------------------------------
__global__ void __launch_bounds__(256, 3) k_qkv(
    const float* __restrict__ X, const float* __restrict__ gamma,
    const float* __restrict__ beta, int d)
{
    extern __shared__ char smem[];
    const uint32_t sbA = smem_u32(smem);
    const uint32_t sbB = sbA + 17408;
    const int tid = threadIdx.x, wid = tid >> 5, lane = tid & 31;
    const int wm = wid >> 2, wn = wid & 3;
    const int m0 = blockIdx.x * 64;
    const __nv_bfloat16* wt = g_wt + (size_t)d * 196608;

    const uint32_t aBase = sbA + (uint32_t)((wm * 32 + (lane & 15)) * 272 + (lane >> 4) * 16);
    const uint32_t bBase = sbB + (uint32_t)((wn * 32 + ((lane >> 4) * 8) + (lane & 7)) * 272
                                            + ((lane >> 3) & 1) * 16);

    {   // stage A: LN1(x) from GLOBAL fp32 x (64 rows, 4 threads/row)
        const int m = tid >> 2, q = tid & 3;
        const float* ap = X + (size_t)(m0 + m) * 128 + q * 32;
        float4 v[8];
#pragma unroll
        for (int j = 0; j < 8; j++) v[j] = ((const float4*)ap)[j];
        float s = 0.f, sq = 0.f;
#pragma unroll
        for (int j = 0; j < 8; j++) {
            s  += v[j].x + v[j].y + v[j].z + v[j].w;
            sq += v[j].x*v[j].x + v[j].y*v[j].y + v[j].z*v[j].z + v[j].w*v[j].w;
        }
        s  += __shfl_xor_sync(0xffffffffu, s , 1);
        sq += __shfl_xor_sync(0xffffffffu, sq, 1);
        s  += __shfl_xor_sync(0xffffffffu, s , 2);
        sq += __shfl_xor_sync(0xffffffffu, sq, 2);
        const float mean = s * (1.f / 128.f);
        const float rstd = rsqrtf(sq * (1.f / 128.f) - mean * mean + 1e-3f);
        char* arow = smem + (size_t)m * 272 + q * 64;
#pragma unroll
        for (int j = 0; j < 4; j++) {
            const int k = q * 32 + j * 8;
            const float4 f0 = v[2*j], f1 = v[2*j+1];
            const float4 g0 = *(const float4*)(gamma + k);
            const float4 g1 = *(const float4*)(gamma + k + 4);
            const float4 b0 = *(const float4*)(beta + k);
            const float4 b1 = *(const float4*)(beta + k + 4);
            __nv_bfloat16 t8[8];
            t8[0]=__float2bfloat16((f0.x-mean)*rstd*g0.x+b0.x);
            t8[1]=__float2bfloat16((f0.y-mean)*rstd*g0.y+b0.y);
            t8[2]=__float2bfloat16((f0.z-mean)*rstd*g0.z+b0.z);
            t8[3]=__float2bfloat16((f0.w-mean)*rstd*g0.w+b0.w);
            t8[4]=__float2bfloat16((f1.x-mean)*rstd*g1.x+b1.x);
            t8[5]=__float2bfloat16((f1.y-mean)*rstd*g1.y+b1.y);
            t8[6]=__float2bfloat16((f1.z-mean)*rstd*g1.z+b1.z);
            t8[7]=__float2bfloat16((f1.w-mean)*rstd*g1.w+b1.w);
            *(uint4*)(arow + j * 16) = *(const uint4*)t8;
        }
    }

    for (int nb = 0; nb < 3; nb++) {
        if (nb) __syncthreads();
        stage_B(smem + 17408, wt + (size_t)nb * 16384, tid);
        __syncthreads();
        float acc[2][4][4] = {};
        gemm_64x128(acc, aBase, bBase);
#pragma unroll
        for (int mt = 0; mt < 2; mt++)
#pragma unroll
            for (int nt = 0; nt < 4; nt++) {
                const int r = m0 + wm * 32 + mt * 16 + (lane >> 2);
                const int c = nb * 128 + wn * 32 + nt * 8 + (lane & 3) * 2;
#pragma unroll
                for (int hrow = 0; hrow < 2; hrow++)
                    *(__nv_bfloat162*)(g_qkv + (size_t)(r + hrow * 8) * 384 + c) =
                        __floats2bfloat162_rn(acc[mt][nt][hrow*2], acc[mt][nt][hrow*2+1]);
            }
    }
}

// ---------------------------------------------------------------------------
// FUSED (v3): CTA = 128 tokens, 256 threads, 8 warps as 2M x 4N, warp tile 64x32.
// x += o@Wp + bp; y = LN2(x); h_i = gelu(y@W1_i+b1_i); x += sum h_i@W2_i + b2;
// then (do_qkv) LN1_next(x) + qkv GEMMs for layer d+1 from smem Xs.
// smem: A 34816 @0, B 34816 @34816, H 34816 @69632, Xs fp32 128x132 @104448.
// Total 172032 B -> 1 CTA/SM (crossbar traffic per output halves vs 32x32 tiles).
// ---------------------------------------------------------------------------
__global__ void __launch_bounds__(256) k_fused(
    const float* __restrict__ bp, const float* __restrict__ ln2_g,
    const float* __restrict__ ln2_b, const float* __restrict__ b1,
    const float* __restrict__ b2, float* __restrict__ X, int d,
    const float* __restrict__ ln1g_n, const float* __restrict__ ln1b_n, int do_qkv)
{
    extern __shared__ char smem[];
    const uint32_t sbA = smem_u32(smem);
    const uint32_t sbB = sbA + 34816;
    const uint32_t sbH = sbA + 69632;
    float* Xs = (float*)(smem + 104448);             // [128][132] fp32
    const int tid = threadIdx.x, wid = tid >> 5, lane = tid & 31;
    const int wm = wid >> 2, wn = wid & 3;           // 2 M-warps x 4 N-warps
    const int m0 = blockIdx.x * 128;
    const __nv_bfloat16* wt = g_wt + (size_t)d * 196608;

    const uint32_t lA = (uint32_t)((wm * 64 + (lane & 15)) * 272 + (lane >> 4) * 16);
    const uint32_t aBase = sbA + lA;
    const uint32_t hBase = sbH + lA;
    const uint32_t bBase = sbB + (uint32_t)((wn * 32 + ((lane >> 4) * 8) + (lane & 7)) * 272
                                            + ((lane >> 3) & 1) * 16);

    // ---- phase 1: proj ----
    {   // stage A = o tile (128 rows, 2 threads/row), B = proj image
        const int m = tid >> 1, h = tid & 1;
        const __nv_bfloat16* ap = g_o + (size_t)(m0 + m) * 128 + h * 64;
        char* arow = smem + (size_t)m * 272 + h * 128;
#pragma unroll
        for (int j = 0; j < 8; j++)
            *(uint4*)(arow + j * 16) = ((const uint4*)ap)[j];
        stage_B(smem + 34816, wt + 3 * 16384, tid);
    }
    __syncthreads();
    {
        float acc[4][4][4] = {};
        gemm_128x128(acc, aBase, bBase);
#pragma unroll
        for (int mt = 0; mt < 4; mt++)
#pragma unroll
            for (int nt = 0; nt < 4; nt++) {
                const int rl = wm * 64 + mt * 16 + (lane >> 2);
                const int c  = wn * 32 + nt * 8 + (lane & 3) * 2;
                const float2 bv = *(const float2*)(bp + c);
#pragma unroll
                for (int hrow = 0; hrow < 2; hrow++) {
                    const int rr = rl + hrow * 8;
                    const float2 xo = *(const float2*)(X + (size_t)(m0 + rr) * 128 + c);
                    *(float2*)&Xs[rr * 132 + c] = make_float2(
                        xo.x + acc[mt][nt][hrow*2]   + bv.x,
                        xo.y + acc[mt][nt][hrow*2+1] + bv.y);
                }
            }
    }
    __syncthreads();

    // ---- phase 2: LN2 from Xs -> A ----
    ln_rows128(smem, Xs, ln2_g, ln2_b, tid);

    // ---- phase 3: interleaved ff1/ff2 over 4 128-col chunks ----
    float acc2[4][4][4] = {};
    for (int i = 0; i < 4; i++) {
        __syncthreads();                          // B/H safe to overwrite
        stage_B(smem + 34816, wt + (size_t)(4 + i) * 16384, tid);
        __syncthreads();
        {   // h_i = gelu(y @ W1_i + b1_i) -> H smem (bf16)
            float acc[4][4][4] = {};
            gemm_128x128(acc, aBase, bBase);
#pragma unroll
            for (int mt = 0; mt < 4; mt++)
#pragma unroll
                for (int nt = 0; nt < 4; nt++) {
                    const int rl = wm * 64 + mt * 16 + (lane >> 2);
                    const int c  = wn * 32 + nt * 8 + (lane & 3) * 2;
                    const float2 bv = *(const float2*)(b1 + i * 128 + c);
#pragma unroll
                    for (int hrow = 0; hrow < 2; hrow++) {
                        const int rr = rl + hrow * 8;
                        *(__nv_bfloat162*)(smem + 69632 + (size_t)rr * 272 + c * 2) =
                            __floats2bfloat162_rn(gelu_exact(acc[mt][nt][hrow*2]   + bv.x),
                                                  gelu_exact(acc[mt][nt][hrow*2+1] + bv.y));
                    }
                }
        }
        __syncthreads();                          // H ready; B readers done
        stage_B(smem + 34816, wt + (size_t)(8 + i) * 16384, tid);
        __syncthreads();
        gemm_128x128(acc2, hBase, bBase);         // acc2 += h_i @ W2_i
    }

    // ---- final epilogue: X = Xs + acc2 + b2 (global + back into Xs) ----
#pragma unroll
    for (int mt = 0; mt < 4; mt++)
#pragma unroll
        for (int nt = 0; nt < 4; nt++) {
            const int rl = wm * 64 + mt * 16 + (lane >> 2);
            const int c  = wn * 32 + nt * 8 + (lane & 3) * 2;
            const float2 bv = *(const float2*)(b2 + c);
#pragma unroll
            for (int hrow = 0; hrow < 2; hrow++) {
                const int rr = rl + hrow * 8;
                const float2 xs = *(const float2*)&Xs[rr * 132 + c];
                const float2 vo = make_float2(xs.x + acc2[mt][nt][hrow*2]   + bv.x,
                                              xs.y + acc2[mt][nt][hrow*2+1] + bv.y);
                *(float2*)(X + (size_t)(m0 + rr) * 128 + c) = vo;
                *(float2*)&Xs[rr * 132 + c] = vo;
            }
        }

    // ---- phase 4 (fused qkv for layer d+1): LN1(Xs) -> A; 3 gemms -> g_qkv ----
    if (do_qkv) {
        __syncthreads();                          // Xs final; A free
        ln_rows128(smem, Xs, ln1g_n, ln1b_n, tid);
        const __nv_bfloat16* wtn = g_wt + (size_t)(d + 1) * 196608;
        for (int nb = 0; nb < 3; nb++) {
            __syncthreads();                      // B free (prev gemm done)
            stage_B(smem + 34816, wtn + (size_t)nb * 16384, tid);
            __syncthreads();
            float acc[4][4][4] = {};
            gemm_128x128(acc, aBase, bBase);
#pragma unroll
            for (int mt = 0; mt < 4; mt++)
#pragma unroll
                for (int nt = 0; nt < 4; nt++) {
                    const int r = m0 + wm * 64 + mt * 16 + (lane >> 2);
                    const int c = nb * 128 + wn * 32 + nt * 8 + (lane & 3) * 2;
#pragma unroll
                    for (int hrow = 0; hrow < 2; hrow++)
                        *(__nv_bfloat162*)(g_qkv + (size_t)(r + hrow * 8) * 384 + c) =
                            __floats2bfloat162_rn(acc[mt][nt][hrow*2], acc[mt][nt][hrow*2+1]);
                }
        }
    }
}

// ---------------------------------------------------------------------------
// Local 3x3 attention (R15 winner, unchanged): bf16 smem halo, pitch 40,
// direct q/o global<->reg. smem = 51840 B.
// ---------------------------------------------------------------------------
#define HP 40

__global__ __launch_bounds__(256) void k_attn()
{
    extern __shared__ __nv_bfloat16 sm16[];
    __nv_bfloat16* ksh = sm16;                 // 324 x HP
    __nv_bfloat16* vsh = sm16 + 324 * HP;
    const int tid = threadIdx.x;
    const int b   = blockIdx.z;
    const int ti0 = blockIdx.y * 16, tj0 = blockIdx.x * 16;
    const size_t img_base = (size_t)b * (SPATIAL * SPATIAL);
    const int lti = tid >> 4, ltj = tid & 15;
    const size_t my_tok = img_base + (size_t)(ti0 + lti) * SPATIAL + (tj0 + ltj);

    for (int head = 0; head < 4; head++) {
        if (head) __syncthreads();
        const int qoff = head * 32, koff = 128 + head * 32, voff = 256 + head * 32;

        for (int u = tid; u < 324 * 4; u += 256) {
            const int rc = u >> 2, c8 = u & 3;
            const int r = rc / 18, cl = rc % 18;
            const int gi = ti0 + r - 1, gj = tj0 + cl - 1;
            uint4 kv = make_uint4(0, 0, 0, 0), vv = make_uint4(0, 0, 0, 0);
            if (gi >= 0 && gi < SPATIAL && gj >= 0 && gj < SPATIAL) {
                const __nv_bfloat16* p = g_qkv + (img_base + (size_t)gi * SPATIAL + gj) * 384;
                kv = *(const uint4*)(p + koff + c8 * 8);
                vv = *(const uint4*)(p + voff + c8 * 8);
            }
            *(uint4*)(ksh + rc * HP + c8 * 8) = kv;
            *(uint4*)(vsh + rc * HP + c8 * 8) = vv;
        }
        float q[32];
        {
            const __nv_bfloat16* qp = g_qkv + my_tok * 384 + qoff;
#pragma unroll
            for (int j = 0; j < 4; j++) {
                const uint4 u4 = *(const uint4*)(qp + j * 8);
                const uint32_t* w = (const uint32_t*)&u4;
#pragma unroll
                for (int h2 = 0; h2 < 4; h2++) {
                    const float2 f = __bfloat1622float2(*(const __nv_bfloat162*)&w[h2]);
                    q[j*8 + h2*2] = f.x; q[j*8 + h2*2 + 1] = f.y;
                }
            }
        }
        __syncthreads();

        float lg[9];
#pragma unroll
        for (int nb = 0; nb < 9; nb++) {
            const __nv_bfloat16* kp = ksh + ((lti + nb/3) * 18 + (ltj + nb%3)) * HP;
            float dd = 0.f;
#pragma unroll
            for (int j = 0; j < 4; j++) {
                const uint4 u4 = *(const uint4*)(kp + j * 8);
                const uint32_t* w = (const uint32_t*)&u4;
#pragma unroll
                for (int h2 = 0; h2 < 4; h2++) {
                    const float2 f = __bfloat1622float2(*(const __nv_bfloat162*)&w[h2]);
                    dd += q[j*8 + h2*2] * f.x + q[j*8 + h2*2 + 1] * f.y;
                }
            }
            lg[nb] = dd * 0.17677669529663687f;
        }
        float mx = lg[0];
#pragma unroll
        for (int nb = 1; nb < 9; nb++) mx = fmaxf(mx, lg[nb]);
        float p9[9], Z = 0.f;
#pragma unroll
        for (int nb = 0; nb < 9; nb++) { p9[nb] = expf(lg[nb] - mx); Z += p9[nb]; }
        const float inv = 1.f / Z;

        float o[32] = {};
#pragma unroll
        for (int nb = 0; nb < 9; nb++) {
            const float wgt = p9[nb] * inv;
            const __nv_bfloat16* vp = vsh + ((lti + nb/3) * 18 + (ltj + nb%3)) * HP;
#pragma unroll
            for (int j = 0; j < 4; j++) {
                const uint4 u4 = *(const uint4*)(vp + j * 8);
                const uint32_t* w = (const uint32_t*)&u4;
#pragma unroll
                for (int h2 = 0; h2 < 4; h2++) {
                    const float2 f = __bfloat1622float2(*(const __nv_bfloat162*)&w[h2]);
                    o[j*8 + h2*2]     += wgt * f.x;
                    o[j*8 + h2*2 + 1] += wgt * f.y;
                }
            }
        }
        {
            __nv_bfloat16* op = g_o + my_tok * 128 + head * 32;
#pragma unroll
            for (int j = 0; j < 4; j++) {
                uint4 u4;
                uint32_t* w = (uint32_t*)&u4;
#pragma unroll
                for (int h2 = 0; h2 < 4; h2++) {
                    const __nv_bfloat162 bb = __floats2bfloat162_rn(
                        o[j*8 + h2*2], o[j*8 + h2*2 + 1]);
                    w[h2] = *(const uint32_t*)&bb;
                }
                *(uint4*)(op + j * 8) = u4;
            }
        }
    }
}

// ---------------------------------------------------------------------------
extern "C" void kernel_launch(void* const* d_in, const int* in_sizes, int n_in,
                              void* d_out, int out_size)
{
    (void)in_sizes; (void)n_in; (void)out_size;
    const float* x_in  = (const float*)d_in[0];
    const float* ln1_g = (const float*)d_in[1];
    const float* ln1_b = (const float*)d_in[2];
    const float* qkv_w = (const float*)d_in[3];
    const float* out_w = (const float*)d_in[4];
    const float* out_b = (const float*)d_in[5];
    const float* ln2_g = (const float*)d_in[6];
    const float* ln2_b = (const float*)d_in[7];
    const float* ff_w1 = (const float*)d_in[8];
    const float* ff_b1 = (const float*)d_in[9];
    const float* ff_w2 = (const float*)d_in[10];
    const float* ff_b2 = (const float*)d_in[11];
    float* X = (float*)d_out;

    const int SM_QKV   = 52224;
    const int SM_FUSED = 172032;
    const int SM_ATTN  = 324 * HP * 2 * 2;      // 51840 B
    cudaFuncSetAttribute(k_qkv,   cudaFuncAttributeMaxDynamicSharedMemorySize, SM_QKV);
    cudaFuncSetAttribute(k_fused, cudaFuncAttributeMaxDynamicSharedMemorySize, SM_FUSED);
    cudaFuncSetAttribute(k_attn,  cudaFuncAttributeMaxDynamicSharedMemorySize, SM_ATTN);

    cudaMemcpyAsync(X, x_in, (size_t)MTOT * 128 * sizeof(float),
                    cudaMemcpyDeviceToDevice, 0);
    k_prep<<<3072, 256>>>(qkv_w, out_w, ff_w1, ff_w2);

    dim3 gAttn(8, 8, 8);
    k_qkv<<<MTOT / 64, 256, SM_QKV>>>(X, ln1_g, ln1_b, 0);   // layer 0 qkv
    for (int d = 0; d < 4; d++) {
        const int dn = (d + 1) & 3;
        k_attn<<<gAttn, 256, SM_ATTN>>>();
        k_fused<<<MTOT / 128, 256, SM_FUSED>>>(out_b + d*128, ln2_g + d*128, ln2_b + d*128,
                                               ff_b1 + d*512, ff_b2 + d*128, X, d,
                                               ln1_g + dn*128, ln1_b + dn*128, (d < 3) ? 1 : 0);
    }
}

// round 17
// speedup vs baseline: 1.3732x; 1.0200x over previous
#include <cuda_runtime.h>
#include <cuda_bf16.h>
#include <math.h>
#include <stdint.h>

#define MTOT 131072
#define SPATIAL 128

__device__ __align__(256) __nv_bfloat16 g_qkv[(size_t)MTOT * 384];
__device__ __align__(256) __nv_bfloat16 g_o  [(size_t)MTOT * 128];
__device__ __align__(256) __nv_bfloat16 g_wt [786432];  // 4 layers x 12 images x [128n][128k]

__device__ __forceinline__ float gelu_exact(float a) {
    return 0.5f * a * (1.0f + erff(a * 0.70710678118654752440f));
}

__device__ __forceinline__ uint32_t smem_u32(const void* p) {
    uint32_t a;
    asm("{ .reg .u64 t; cvta.to.shared.u64 t, %1; cvt.u32.u64 %0, t; }" : "=r"(a) : "l"(p));
    return a;
}

#define LDSM4(r0, r1, r2, r3, addr) \
    asm volatile("ldmatrix.sync.aligned.m8n8.x4.shared.b16 {%0,%1,%2,%3}, [%4];" \
                 : "=r"(r0), "=r"(r1), "=r"(r2), "=r"(r3) : "r"(addr))

#define MMA16816(d, a, b) \
    asm volatile("mma.sync.aligned.m16n8k16.row.col.f32.bf16.bf16.f32 " \
                 "{%0,%1,%2,%3},{%4,%5,%6,%7},{%8,%9},{%0,%1,%2,%3};" \
                 : "+f"((d)[0]), "+f"((d)[1]), "+f"((d)[2]), "+f"((d)[3]) \
                 : "r"((a)[0]), "r"((a)[1]), "r"((a)[2]), "r"((a)[3]), \
                   "r"((b)[0]), "r"((b)[1]))

#define CPA16(dst, src) \
    asm volatile("cp.async.cg.shared.global [%0], [%1], 16;" :: "r"(dst), "l"(src) : "memory")
#define CPA_COMMIT() asm volatile("cp.async.commit_group;" ::: "memory")
#define CPA_WAIT1()  asm volatile("cp.async.wait_group 1;" ::: "memory")
#define CPA_WAIT0()  asm volatile("cp.async.wait_group 0;" ::: "memory")

__device__ __forceinline__ void cpa_wait(bool last) { if (last) CPA_WAIT0(); else CPA_WAIT1(); }

// ---------------------------------------------------------------------------
// Prep: transpose weights to n-major/k-contig bf16 images [128n][128k].
// Per layer (12 imgs): 0-2 qkv n-blocks, 3 proj, 4-7 ff1 n-blocks, 8-11 ff2 k-chunks.
// ---------------------------------------------------------------------------
__global__ __launch_bounds__(256) void k_prep(
    const float* __restrict__ qkv_w, const float* __restrict__ out_w,
    const float* __restrict__ ff_w1, const float* __restrict__ ff_w2)
{
    const int idx = blockIdx.x * 256 + threadIdx.x;   // 0..786431
    const int d   = idx / 196608;
    const int rem = idx % 196608;
    const int img = rem / 16384;
    const int pos = rem % 16384;
    const int n = pos >> 7, k = pos & 127;
    float val;
    if (img < 3)       val = qkv_w[(size_t)(d * 128 + k) * 384 + img * 128 + n];
    else if (img == 3) val = out_w[(size_t)(d * 128 + k) * 128 + n];
    else if (img < 8)  val = ff_w1[(size_t)(d * 128 + k) * 512 + (img - 4) * 128 + n];
    else               val = ff_w2[(size_t)(d * 512 + (img - 8) * 128 + k) * 128 + n];
    g_wt[idx] = __float2bfloat16(val);
}

// ---------------------------------------------------------------------------
// Shared helpers. Row stride 272 B -> conflict-free ldmatrix.
// ---------------------------------------------------------------------------
__device__ __forceinline__ void stage_B(char* bs, const __nv_bfloat16* img, int tid) {
    const uint4* s4 = (const uint4*)img;
#pragma unroll
    for (int i = 0; i < 8; i++) {
        const int u = tid + i * 256;
        const int row = u >> 4, c8 = u & 15;
        *(uint4*)(bs + (size_t)row * 272 + c8 * 16) = s4[u];
    }
}

// cp.async version: fire-and-forget, no register round-trip.
__device__ __forceinline__ void cpa_stage_B(uint32_t bs, const __nv_bfloat16* img, int tid) {
#pragma unroll
    for (int i = 0; i < 8; i++) {
        const int u = tid + i * 256;
        const int row = u >> 4, c8 = u & 15;
        CPA16(bs + (uint32_t)(row * 272 + c8 * 16), (const char*)img + (size_t)u * 16);
    }
}

// Warp tile 32x32 (standalone k_qkv)
__device__ __forceinline__ void gemm_64x128(
    float acc[2][4][4], uint32_t aBase, uint32_t bBase)
{
#pragma unroll
    for (int kk = 0; kk < 8; kk++) {
        uint32_t a[2][4];
#pragma unroll
        for (int mt = 0; mt < 2; mt++)
            LDSM4(a[mt][0], a[mt][1], a[mt][2], a[mt][3],
                  aBase + (uint32_t)(mt * 16 * 272 + kk * 32));
        uint32_t b[4][2];
#pragma unroll
        for (int nt2 = 0; nt2 < 2; nt2++)
            LDSM4(b[nt2*2][0], b[nt2*2][1], b[nt2*2+1][0], b[nt2*2+1][1],
                  bBase + (uint32_t)(nt2 * 16 * 272 + kk * 32));
#pragma unroll
        for (int mt = 0; mt < 2; mt++)
#pragma unroll
            for (int nt = 0; nt < 4; nt++)
                MMA16816(acc[mt][nt], a[mt], b[nt]);
    }
}

// Warp tile 64x32 (fused kernel)
__device__ __forceinline__ void gemm_128x128(
    float acc[4][4][4], uint32_t aBase, uint32_t bBase)
{
#pragma unroll
    for (int kk = 0; kk < 8; kk++) {
        uint32_t a[4][4];
#pragma unroll
        for (int mt = 0; mt < 4; mt++)
            LDSM4(a[mt][0], a[mt][1], a[mt][2], a[mt][3],
                  aBase + (uint32_t)(mt * 16 * 272 + kk * 32));
        uint32_t b[4][2];
#pragma unroll
        for (int nt2 = 0; nt2 < 2; nt2++)
            LDSM4(b[nt2*2][0], b[nt2*2][1], b[nt2*2+1][0], b[nt2*2+1][1],
                  bBase + (uint32_t)(nt2 * 16 * 272 + kk * 32));
#pragma unroll
        for (int mt = 0; mt < 4; mt++)
#pragma unroll
            for (int nt = 0; nt < 4; nt++)
                MMA16816(acc[mt][nt], a[mt], b[nt]);
    }
}

// LayerNorm of 128 rows from fp32 smem tile (stride 132) -> bf16 A tile (stride 272).
__device__ __forceinline__ void ln_rows128(
    char* smem, const float* Xs, const float* g, const float* b, int tid)
{
    const int m = tid >> 1, h = tid & 1;
    const float* xp = &Xs[m * 132 + h * 64];
    float4 v[16];
#pragma unroll
    for (int j = 0; j < 16; j++) v[j] = ((const float4*)xp)[j];
    float s = 0.f, sq = 0.f;
#pragma unroll
    for (int j = 0; j < 16; j++) {
        s  += v[j].x + v[j].y + v[j].z + v[j].w;
        sq += v[j].x*v[j].x + v[j].y*v[j].y + v[j].z*v[j].z + v[j].w*v[j].w;
    }
    s  += __shfl_xor_sync(0xffffffffu, s , 1);
    sq += __shfl_xor_sync(0xffffffffu, sq, 1);
    const float mean = s * (1.f / 128.f);
    const float rstd = rsqrtf(sq * (1.f / 128.f) - mean * mean + 1e-3f);
    char* arow = smem + (size_t)m * 272 + h * 128;
#pragma unroll
    for (int j = 0; j < 8; j++) {
        const int k = h * 64 + j * 8;
        const float4 f0 = v[2*j], f1 = v[2*j+1];
        const float4 g0 = *(const float4*)(g + k);
        const float4 g1 = *(const float4*)(g + k + 4);
        const float4 c0 = *(const float4*)(b + k);
        const float4 c1 = *(const float4*)(b + k + 4);
        __nv_bfloat16 t8[8];
        t8[0]=__float2bfloat16((f0.x-mean)*rstd*g0.x+c0.x);
        t8[1]=__float2bfloat16((f0.y-mean)*rstd*g0.y+c0.y);
        t8[2]=__float2bfloat16((f0.z-mean)*rstd*g0.z+c0.z);
        t8[3]=__float2bfloat16((f0.w-mean)*rstd*g0.w+c0.w);
        t8[4]=__float2bfloat16((f1.x-mean)*rstd*g1.x+c1.x);
        t8[5]=__float2bfloat16((f1.y-mean)*rstd*g1.y+c1.y);
        t8[6]=__float2bfloat16((f1.z-mean)*rstd*g1.z+c1.z);
        t8[7]=__float2bfloat16((f1.w-mean)*rstd*g1.w+c1.w);
        *(uint4*)(arow + j * 16) = *(const uint4*)t8;
    }
}

// ---------------------------------------------------------------------------
// Kernel 1 (layer 0 only): y = LN1(x); qkv = y @ Wqkv -> g_qkv bf16. (unchanged)
// ---------------------------------------------------------------------------
__global__ void __launch_bounds__(256, 3) k_qkv(
    const float* __restrict__ X, const float* __restrict__ gamma,
    const float* __restrict__ beta, int d)
{
    extern __shared__ char smem[];
    const uint32_t sbA = smem_u32(smem);
    const uint32_t sbB = sbA + 17408;
    const int tid = threadIdx.x, wid = tid >> 5, lane = tid & 31;
    const int wm = wid >> 2, wn = wid & 3;
    const int m0 = blockIdx.x * 64;
    const __nv_bfloat16* wt = g_wt + (size_t)d * 196608;

    const uint32_t aBase = sbA + (uint32_t)((wm * 32 + (lane & 15)) * 272 + (lane >> 4) * 16);
    const uint32_t bBase = sbB + (uint32_t)((wn * 32 + ((lane >> 4) * 8) + (lane & 7)) * 272
                                            + ((lane >> 3) & 1) * 16);

    {   // stage A: LN1(x) from GLOBAL fp32 x
        const int m = tid >> 2, q = tid & 3;
        const float* ap = X + (size_t)(m0 + m) * 128 + q * 32;
        float4 v[8];
#pragma unroll
        for (int j = 0; j < 8; j++) v[j] = ((const float4*)ap)[j];
        float s = 0.f, sq = 0.f;
#pragma unroll
        for (int j = 0; j < 8; j++) {
            s  += v[j].x + v[j].y + v[j].z + v[j].w;
            sq += v[j].x*v[j].x + v[j].y*v[j].y + v[j].z*v[j].z + v[j].w*v[j].w;
        }
        s  += __shfl_xor_sync(0xffffffffu, s , 1);
        sq += __shfl_xor_sync(0xffffffffu, sq, 1);
        s  += __shfl_xor_sync(0xffffffffu, s , 2);
        sq += __shfl_xor_sync(0xffffffffu, sq, 2);
        const float mean = s * (1.f / 128.f);
        const float rstd = rsqrtf(sq * (1.f / 128.f) - mean * mean + 1e-3f);
        char* arow = smem + (size_t)m * 272 + q * 64;
#pragma unroll
        for (int j = 0; j < 4; j++) {
            const int k = q * 32 + j * 8;
            const float4 f0 = v[2*j], f1 = v[2*j+1];
            const float4 g0 = *(const float4*)(gamma + k);
            const float4 g1 = *(const float4*)(gamma + k + 4);
            const float4 b0 = *(const float4*)(beta + k);
            const float4 b1 = *(const float4*)(beta + k + 4);
            __nv_bfloat16 t8[8];
            t8[0]=__float2bfloat16((f0.x-mean)*rstd*g0.x+b0.x);
            t8[1]=__float2bfloat16((f0.y-mean)*rstd*g0.y+b0.y);
            t8[2]=__float2bfloat16((f0.z-mean)*rstd*g0.z+b0.z);
            t8[3]=__float2bfloat16((f0.w-mean)*rstd*g0.w+b0.w);
            t8[4]=__float2bfloat16((f1.x-mean)*rstd*g1.x+b1.x);
            t8[5]=__float2bfloat16((f1.y-mean)*rstd*g1.y+b1.y);
            t8[6]=__float2bfloat16((f1.z-mean)*rstd*g1.z+b1.z);
            t8[7]=__float2bfloat16((f1.w-mean)*rstd*g1.w+b1.w);
            *(uint4*)(arow + j * 16) = *(const uint4*)t8;
        }
    }

    for (int nb = 0; nb < 3; nb++) {
        if (nb) __syncthreads();
        stage_B(smem + 17408, wt + (size_t)nb * 16384, tid);
        __syncthreads();
        float acc[2][4][4] = {};
        gemm_64x128(acc, aBase, bBase);
#pragma unroll
        for (int mt = 0; mt < 2; mt++)
#pragma unroll
            for (int nt = 0; nt < 4; nt++) {
                const int r = m0 + wm * 32 + mt * 16 + (lane >> 2);
                const int c = nb * 128 + wn * 32 + nt * 8 + (lane & 3) * 2;
#pragma unroll
                for (int hrow = 0; hrow < 2; hrow++)
                    *(__nv_bfloat162*)(g_qkv + (size_t)(r + hrow * 8) * 384 + c) =
                        __floats2bfloat162_rn(acc[mt][nt][hrow*2], acc[mt][nt][hrow*2+1]);
            }
    }
}

// ---------------------------------------------------------------------------
// FUSED (v4): CTA = 128 tokens, 256 threads, warp tile 64x32, cp.async
// double-buffered weight staging. Gemm j uses B[j%2]; copy j+2 issued right
// after the sync freeing B[j%2] and overlaps gemm j+1.
// imgs order: proj, ff1_0, ff2_0, ff1_1, ff2_1, ff1_2, ff2_2, ff1_3, ff2_3,
// [qkv0', qkv1', qkv2'] (layer d+1).
// smem: A 34816 @0, B0 @34816, B1 @69632, H @104448, Xs fp32 @139264 (67584).
// Total 206848 B -> 1 CTA/SM.
// ---------------------------------------------------------------------------
__global__ void __launch_bounds__(256) k_fused(
    const float* __restrict__ bp, const float* __restrict__ ln2_g,
    const float* __restrict__ ln2_b, const float* __restrict__ b1,
    const float* __restrict__ b2, float* __restrict__ X, int d,
    const float* __restrict__ ln1g_n, const float* __restrict__ ln1b_n, int do_qkv)
{
    extern __shared__ char smem[];
    const uint32_t sbA  = smem_u32(smem);
    const uint32_t sbB0 = sbA + 34816;
    const uint32_t sbB1 = sbA + 69632;
    const uint32_t sbH  = sbA + 104448;
    float* Xs = (float*)(smem + 139264);             // [128][132] fp32
    const int tid = threadIdx.x, wid = tid >> 5, lane = tid & 31;
    const int wm = wid >> 2, wn = wid & 3;           // 2 M-warps x 4 N-warps
    const int m0 = blockIdx.x * 128;
    const __nv_bfloat16* wt  = g_wt + (size_t)d * 196608;
    const __nv_bfloat16* wtn = g_wt + (size_t)((d + 1) & 3) * 196608;

    const uint32_t lA = (uint32_t)((wm * 64 + (lane & 15)) * 272 + (lane >> 4) * 16);
    const uint32_t aBase = sbA + lA;
    const uint32_t hBase = sbH + lA;
    const uint32_t lB = (uint32_t)((wn * 32 + ((lane >> 4) * 8) + (lane & 7)) * 272
                                   + ((lane >> 3) & 1) * 16);

    // ---- group 0: A (= o tile) + B0(proj); group 1: B1(ff1_0) ----
    {
        const int m = tid >> 1, h = tid & 1;
        const __nv_bfloat16* ap = g_o + (size_t)(m0 + m) * 128 + h * 64;
        const uint32_t arow = sbA + (uint32_t)(m * 272 + h * 128);
#pragma unroll
        for (int j = 0; j < 8; j++)
            CPA16(arow + j * 16, (const char*)ap + j * 16);
        cpa_stage_B(sbB0, wt + 3 * 16384, tid);
        CPA_COMMIT();
        cpa_stage_B(sbB1, wt + 4 * 16384, tid);
        CPA_COMMIT();
    }

    // ---- g0: proj (B0) ----
    CPA_WAIT1(); __syncthreads();
    {
        float acc[4][4][4] = {};
        gemm_128x128(acc, aBase, sbB0 + lB);
#pragma unroll
        for (int mt = 0; mt < 4; mt++)
#pragma unroll
            for (int nt = 0; nt < 4; nt++) {
                const int rl = wm * 64 + mt * 16 + (lane >> 2);
                const int c  = wn * 32 + nt * 8 + (lane & 3) * 2;
                const float2 bv = *(const float2*)(bp + c);
#pragma unroll
                for (int hrow = 0; hrow < 2; hrow++) {
                    const int rr = rl + hrow * 8;
                    const float2 xo = *(const float2*)(X + (size_t)(m0 + rr) * 128 + c);
                    *(float2*)&Xs[rr * 132 + c] = make_float2(
                        xo.x + acc[mt][nt][hrow*2]   + bv.x,
                        xo.y + acc[mt][nt][hrow*2+1] + bv.y);
                }
            }
    }
    __syncthreads();                                  // Xs visible; B0 free
    cpa_stage_B(sbB0, wt + 8 * 16384, tid); CPA_COMMIT();   // G2 = ff2_0

    // ---- LN2 (overlaps G2 copy) ----
    ln_rows128(smem, Xs, ln2_g, ln2_b, tid);

    // ---- ff loop: g(2i+1)=ff1_i (B1), g(2i+2)=ff2_i (B0) ----
    float acc2[4][4][4] = {};
    for (int i = 0; i < 4; i++) {
        CPA_WAIT1(); __syncthreads();                 // ff1_i staged; LN/A writes visible
        {
            float acc[4][4][4] = {};
            gemm_128x128(acc, aBase, sbB1 + lB);
#pragma unroll
            for (int mt = 0; mt < 4; mt++)
#pragma unroll
                for (int nt = 0; nt < 4; nt++) {
                    const int rl = wm * 64 + mt * 16 + (lane >> 2);
                    const int c  = wn * 32 + nt * 8 + (lane & 3) * 2;
                    const float2 bv = *(const float2*)(b1 + i * 128 + c);
#pragma unroll
                    for (int hrow = 0; hrow < 2; hrow++) {
                        const int rr = rl + hrow * 8;
                        *(__nv_bfloat162*)(smem + 104448 + (size_t)rr * 272 + c * 2) =
                            __floats2bfloat162_rn(gelu_exact(acc[mt][nt][hrow*2]   + bv.x),
                                                  gelu_exact(acc[mt][nt][hrow*2+1] + bv.y));
                    }
                }
        }
        __syncthreads();                              // H ready; B1 free
        if (i < 3) { cpa_stage_B(sbB1, wt + (size_t)(5 + i) * 16384, tid); CPA_COMMIT(); }
        else if (do_qkv) { cpa_stage_B(sbB1, wtn, tid); CPA_COMMIT(); }

        cpa_wait(i == 3 && !do_qkv); __syncthreads(); // ff2_i staged
        gemm_128x128(acc2, hBase, sbB0 + lB);
        __syncthreads();                              // B0 free
        if (i < 3) { cpa_stage_B(sbB0, wt + (size_t)(9 + i) * 16384, tid); CPA_COMMIT(); }
        else if (do_qkv) { cpa_stage_B(sbB0, wtn + 16384, tid); CPA_COMMIT(); }
    }

    // ---- final epilogue: X = Xs + acc2 + b2 (global + back into Xs) ----
#pragma unroll
    for (int mt = 0; mt < 4; mt++)
#pragma unroll
        for (int nt = 0; nt < 4; nt++) {
            const int rl = wm * 64 + mt * 16 + (lane >> 2);
            const int c  = wn * 32 + nt * 8 + (lane & 3) * 2;
            const float2 bv = *(const float2*)(b2 + c);
#pragma unroll
            for (int hrow = 0; hrow < 2; hrow++) {
                const int rr = rl + hrow * 8;
                const float2 xs = *(const float2*)&Xs[rr * 132 + c];
                const float2 vo = make_float2(xs.x + acc2[mt][nt][hrow*2]   + bv.x,
                                              xs.y + acc2[mt][nt][hrow*2+1] + bv.y);
                *(float2*)(X + (size_t)(m0 + rr) * 128 + c) = vo;
                *(float2*)&Xs[rr * 132 + c] = vo;
            }
        }

    // ---- qkv tail for layer d+1: g9..g11 (B1, B0, B1) ----
    if (do_qkv) {
        __syncthreads();                              // Xs final; A free
        ln_rows128(smem, Xs, ln1g_n, ln1b_n, tid);
        for (int nb = 0; nb < 3; nb++) {
            cpa_wait(nb == 2); __syncthreads();       // qkv_nb staged; LN/A visible
            const uint32_t bb = ((nb & 1) ? sbB0 : sbB1) + lB;   // g9:B1 g10:B0 g11:B1
            float acc[4][4][4] = {};
            gemm_128x128(acc, aBase, bb);
#pragma unroll
            for (int mt = 0; mt < 4; mt++)
#pragma unroll
                for (int nt = 0; nt < 4; nt++) {
                    const int r = m0 + wm * 64 + mt * 16 + (lane >> 2);
                    const int c = nb * 128 + wn * 32 + nt * 8 + (lane & 3) * 2;
#pragma unroll
                    for (int hrow = 0; hrow < 2; hrow++)
                        *(__nv_bfloat162*)(g_qkv + (size_t)(r + hrow * 8) * 384 + c) =
                            __floats2bfloat162_rn(acc[mt][nt][hrow*2], acc[mt][nt][hrow*2+1]);
                }
            __syncthreads();                          // buffer free
            if (nb == 0) { cpa_stage_B(sbB1, wtn + 32768, tid); CPA_COMMIT(); }
        }
    }
}

// ---------------------------------------------------------------------------
// Local 3x3 attention (R15 winner, unchanged): bf16 smem halo, pitch 40,
// direct q/o global<->reg. smem = 51840 B.
// ---------------------------------------------------------------------------
#define HP 40

__global__ __launch_bounds__(256) void k_attn()
{
    extern __shared__ __nv_bfloat16 sm16[];
    __nv_bfloat16* ksh = sm16;
    __nv_bfloat16* vsh = sm16 + 324 * HP;
    const int tid = threadIdx.x;
    const int b   = blockIdx.z;
    const int ti0 = blockIdx.y * 16, tj0 = blockIdx.x * 16;
    const size_t img_base = (size_t)b * (SPATIAL * SPATIAL);
    const int lti = tid >> 4, ltj = tid & 15;
    const size_t my_tok = img_base + (size_t)(ti0 + lti) * SPATIAL + (tj0 + ltj);

    for (int head = 0; head < 4; head++) {
        if (head) __syncthreads();
        const int qoff = head * 32, koff = 128 + head * 32, voff = 256 + head * 32;

        for (int u = tid; u < 324 * 4; u += 256) {
            const int rc = u >> 2, c8 = u & 3;
            const int r = rc / 18, cl = rc % 18;
            const int gi = ti0 + r - 1, gj = tj0 + cl - 1;
            uint4 kv = make_uint4(0, 0, 0, 0), vv = make_uint4(0, 0, 0, 0);
            if (gi >= 0 && gi < SPATIAL && gj >= 0 && gj < SPATIAL) {
                const __nv_bfloat16* p = g_qkv + (img_base + (size_t)gi * SPATIAL + gj) * 384;
                kv = *(const uint4*)(p + koff + c8 * 8);
                vv = *(const uint4*)(p + voff + c8 * 8);
            }
            *(uint4*)(ksh + rc * HP + c8 * 8) = kv;
            *(uint4*)(vsh + rc * HP + c8 * 8) = vv;
        }
        float q[32];
        {
            const __nv_bfloat16* qp = g_qkv + my_tok * 384 + qoff;
#pragma unroll
            for (int j = 0; j < 4; j++) {
                const uint4 u4 = *(const uint4*)(qp + j * 8);
                const uint32_t* w = (const uint32_t*)&u4;
#pragma unroll
                for (int h2 = 0; h2 < 4; h2++) {
                    const float2 f = __bfloat1622float2(*(const __nv_bfloat162*)&w[h2]);
                    q[j*8 + h2*2] = f.x; q[j*8 + h2*2 + 1] = f.y;
                }
            }
        }
        __syncthreads();

        float lg[9];
#pragma unroll
        for (int nb = 0; nb < 9; nb++) {
            const __nv_bfloat16* kp = ksh + ((lti + nb/3) * 18 + (ltj + nb%3)) * HP;
            float dd = 0.f;
#pragma unroll
            for (int j = 0; j < 4; j++) {
                const uint4 u4 = *(const uint4*)(kp + j * 8);
                const uint32_t* w = (const uint32_t*)&u4;
#pragma unroll
                for (int h2 = 0; h2 < 4; h2++) {
                    const float2 f = __bfloat1622float2(*(const __nv_bfloat162*)&w[h2]);
                    dd += q[j*8 + h2*2] * f.x + q[j*8 + h2*2 + 1] * f.y;
                }
            }
            lg[nb] = dd * 0.17677669529663687f;
        }
        float mx = lg[0];
#pragma unroll
        for (int nb = 1; nb < 9; nb++) mx = fmaxf(mx, lg[nb]);
        float p9[9], Z = 0.f;
#pragma unroll
        for (int nb = 0; nb < 9; nb++) { p9[nb] = expf(lg[nb] - mx); Z += p9[nb]; }
        const float inv = 1.f / Z;

        float o[32] = {};
#pragma unroll
        for (int nb = 0; nb < 9; nb++) {
            const float wgt = p9[nb] * inv;
            const __nv_bfloat16* vp = vsh + ((lti + nb/3) * 18 + (ltj + nb%3)) * HP;
#pragma unroll
            for (int j = 0; j < 4; j++) {
                const uint4 u4 = *(const uint4*)(vp + j * 8);
                const uint32_t* w = (const uint32_t*)&u4;
#pragma unroll
                for (int h2 = 0; h2 < 4; h2++) {
                    const float2 f = __bfloat1622float2(*(const __nv_bfloat162*)&w[h2]);
                    o[j*8 + h2*2]     += wgt * f.x;
                    o[j*8 + h2*2 + 1] += wgt * f.y;
                }
            }
        }
        {
            __nv_bfloat16* op = g_o + my_tok * 128 + head * 32;
#pragma unroll
            for (int j = 0; j < 4; j++) {
                uint4 u4;
                uint32_t* w = (uint32_t*)&u4;
#pragma unroll
                for (int h2 = 0; h2 < 4; h2++) {
                    const __nv_bfloat162 bb = __floats2bfloat162_rn(
                        o[j*8 + h2*2], o[j*8 + h2*2 + 1]);
                    w[h2] = *(const uint32_t*)&bb;
                }
                *(uint4*)(op + j * 8) = u4;
            }
        }
    }
}

// ---------------------------------------------------------------------------
extern "C" void kernel_launch(void* const* d_in, const int* in_sizes, int n_in,
                              void* d_out, int out_size)
{
    (void)in_sizes; (void)n_in; (void)out_size;
    const float* x_in  = (const float*)d_in[0];
    const float* ln1_g = (const float*)d_in[1];
    const float* ln1_b = (const float*)d_in[2];
    const float* qkv_w = (const float*)d_in[3];
    const float* out_w = (const float*)d_in[4];
    const float* out_b = (const float*)d_in[5];
    const float* ln2_g = (const float*)d_in[6];
    const float* ln2_b = (const float*)d_in[7];
    const float* ff_w1 = (const float*)d_in[8];
    const float* ff_b1 = (const float*)d_in[9];
    const float* ff_w2 = (const float*)d_in[10];
    const float* ff_b2 = (const float*)d_in[11];
    float* X = (float*)d_out;

    const int SM_QKV   = 52224;
    const int SM_FUSED = 206848;
    const int SM_ATTN  = 324 * HP * 2 * 2;      // 51840 B
    cudaFuncSetAttribute(k_qkv,   cudaFuncAttributeMaxDynamicSharedMemorySize, SM_QKV);
    cudaFuncSetAttribute(k_fused, cudaFuncAttributeMaxDynamicSharedMemorySize, SM_FUSED);
    cudaFuncSetAttribute(k_attn,  cudaFuncAttributeMaxDynamicSharedMemorySize, SM_ATTN);

    cudaMemcpyAsync(X, x_in, (size_t)MTOT * 128 * sizeof(float),
                    cudaMemcpyDeviceToDevice, 0);
    k_prep<<<3072, 256>>>(qkv_w, out_w, ff_w1, ff_w2);

    dim3 gAttn(8, 8, 8);
    k_qkv<<<MTOT / 64, 256, SM_QKV>>>(X, ln1_g, ln1_b, 0);   // layer 0 qkv
    for (int d = 0; d < 4; d++) {
        const int dn = (d + 1) & 3;
        k_attn<<<gAttn, 256, SM_ATTN>>>();
        k_fused<<<MTOT / 128, 256, SM_FUSED>>>(out_b + d*128, ln2_g + d*128, ln2_b + d*128,
                                               ff_b1 + d*512, ff_b2 + d*128, X, d,
                                               ln1_g + dn*128, ln1_b + dn*128, (d < 3) ? 1 : 0);
    }
}